// round 5
// baseline (speedup 1.0000x reference)
#include <cuda_runtime.h>
#include <cstddef>

#define T_STEPS 32
#define NB      64
#define LEN0    2048
#define L1      1023
#define L2      511
#define C1      32
#define C2      64

// ---- output layout offsets ----
static const size_t O_SPK0 = 0;
static const size_t O_SPK1 = (size_t)T_STEPS*NB*32736;
static const size_t O_SPK2 = O_SPK1 + (size_t)T_STEPS*NB*32704;
static const size_t O_SPK3 = O_SPK2 + (size_t)T_STEPS*NB*256;
static const size_t O_MEM0 = O_SPK3 + (size_t)T_STEPS*NB*2;
static const size_t O_MEM1 = O_MEM0 + (size_t)T_STEPS*NB*32736;
static const size_t O_MEM2 = O_MEM1 + (size_t)T_STEPS*NB*32704;
static const size_t O_MEM3 = O_MEM2 + (size_t)T_STEPS*NB*256;

// ---- persistent state / scratch ----
__device__ float    g_mem0[NB*C1*L1];
__device__ float    g_mem1[NB*C2*L2];
__device__ float    g_mem2[NB*256];
__device__ float    g_mem3[NB*2];
__device__ unsigned g_mask[2][NB*L1];     // double-buffered spike bitmasks
__device__ float    g_feat[2*NB*128];     // double-buffered avgpool features
// LUT: [grp(16)][kb(12)][v(256)] float4 (4 oc per group)
__device__ __align__(16) float g_lut[16*12*256*4];

// smem layout for fused kernel (stage2 role): LUT 48KB + masks + aux
#define SM_T    0
#define SM_MASK 49152
#define SM_AUX  (49152 + 4128)
#define SMEM2   (SM_AUX + 96)

// ================= compensated-arithmetic helpers =================
__device__ __forceinline__ void twoSum(float a, float b, float& s, float& e) {
    s = a + b;
    float bp = s - a;
    float ap = s - bp;
    e = (b - bp) + (a - ap);
}
__device__ __forceinline__ void kadd(float& s, float& c, float v) {
    float t, e;
    twoSum(s, v, t, e);
    c += e;
    s = t;
}
__device__ __forceinline__ void kfma(float& s, float& c, float a, float b) {
    float p = a * b;
    float e = fmaf(a, b, -p);
    kadd(s, c, p);
    c += e;
}

// ================= init: zero membrane states =================
__global__ void k_init() {
    const int n0 = NB*C1*L1, n1 = NB*C2*L2, n2 = NB*256, n3 = NB*2;
    const int n = n0 + n1 + n2 + n3;
    for (int i = blockIdx.x*blockDim.x + threadIdx.x; i < n; i += gridDim.x*blockDim.x) {
        if (i < n0) g_mem0[i] = 0.f;
        else if (i < n0+n1) g_mem1[i-n0] = 0.f;
        else if (i < n0+n1+n2) g_mem2[i-n0-n1] = 0.f;
        else g_mem3[i-n0-n1-n2] = 0.f;
    }
}

// ================= LUT build (double, rounded once) =================
__global__ void k_lut(const float* __restrict__ w2) {
    int i = blockIdx.x*blockDim.x + threadIdx.x;
    if (i >= 16*12*256*4) return;
    int ocl = i & 3;
    int v   = (i >> 2) & 255;
    int tt  = i >> 10;
    int kb  = tt % 12;
    int g   = tt / 12;
    int k   = kb >> 2;
    int b4  = kb & 3;
    int oc  = g*4 + ocl;
    double s = 0.0;
    #pragma unroll
    for (int bit = 0; bit < 8; bit++)
        if ((v >> bit) & 1)
            s += (double)w2[(oc*32 + b4*8 + bit)*3 + k];
    g_lut[i] = (float)s;
}

// ================= stage1 body: conv1 + maxpool + LIF0 =================
__device__ __forceinline__ void stage1_body(
        float* sw, float* sb, float* sthr,
        int b, int tile, int ts,
        const float* __restrict__ x, const float* __restrict__ w1,
        const float* __restrict__ b1, const float* __restrict__ thr,
        float* __restrict__ out)
{
    for (int i = threadIdx.x; i < C1*12; i += 256) sw[i] = w1[i];
    if (threadIdx.x < C1) sb[threadIdx.x] = b1[threadIdx.x];
    if (threadIdx.x == 0) sthr[0] = thr[0];
    __syncthreads();

    int l1 = tile*256 + threadIdx.x;
    if (l1 >= L1) return;

    const float* xb = x + (((size_t)b*T_STEPS + ts)*4)*LEN0;
    float xr[4][5];
    #pragma unroll
    for (int c = 0; c < 4; c++)
        #pragma unroll
        for (int j = 0; j < 5; j++) {
            int gi = 2*l1 - 1 + j;
            xr[c][j] = (gi >= 0 && gi < LEN0) ? xb[c*LEN0 + gi] : 0.f;
        }

    const float th = sthr[0];
    unsigned mask = 0;
    #pragma unroll 2
    for (int oc = 0; oc < C1; oc++) {
        float bb = sb[oc];
        float y0 = bb, y1 = bb, y2 = bb;
        #pragma unroll
        for (int c = 0; c < 4; c++) {
            float w0 = sw[oc*12 + c*3 + 0];
            float w1v = sw[oc*12 + c*3 + 1];
            float w2v = sw[oc*12 + c*3 + 2];
            y0 = fmaf(w0, xr[c][0], fmaf(w1v, xr[c][1], fmaf(w2v, xr[c][2], y0)));
            y1 = fmaf(w0, xr[c][1], fmaf(w1v, xr[c][2], fmaf(w2v, xr[c][3], y1)));
            y2 = fmaf(w0, xr[c][2], fmaf(w1v, xr[c][3], fmaf(w2v, xr[c][4], y2)));
        }
        int dmax = 0;
        float ymax = y0;
        if (y1 > ymax) { ymax = y1; dmax = 1; }
        if (y2 > ymax) { ymax = y2; dmax = 2; }

        float s = bb, cc = 0.f;
        #pragma unroll
        for (int c = 0; c < 4; c++) {
            #pragma unroll
            for (int k = 0; k < 3; k++)
                kfma(s, cc, sw[oc*12 + c*3 + k], xr[c][dmax + k]);
        }
        float cur = s + cc;

        int   sidx = (b*C1 + oc)*L1 + l1;
        float mem  = g_mem0[sidx];
        float rst  = (mem - th > 0.f) ? 1.f : 0.f;
        float memn = fmaf(0.5f, mem, cur) - rst*th;
        g_mem0[sidx] = memn;
        float spk = (memn - th > 0.f) ? 1.f : 0.f;
        if (spk > 0.f) mask |= (1u << oc);
        size_t oi = ((size_t)ts*NB + b)*32736 + (size_t)oc*L1 + l1;
        out[O_SPK0 + oi] = spk;
        out[O_MEM0 + oi] = memn;
    }
    g_mask[ts & 1][b*L1 + l1] = mask;
}

// ================= fc body (fc1 + LIF2 + fc2 + LIF3) for step ts ============
__device__ __forceinline__ void fc_block(
        char* sm, int b, int ts,
        const float* __restrict__ fc1w, const float* __restrict__ fc1b,
        const float* __restrict__ fc2w, const float* __restrict__ fc2b,
        const float* __restrict__ thr, float* __restrict__ out)
{
    float* sfeat = (float*)sm;          // 128
    float* sfc1o = sfeat + 128;         // 256
    float* sspk2 = sfc1o + 256;         // 256
    int tid = threadIdx.x;

    if (tid < 128) sfeat[tid] = g_feat[(size_t)(ts&1)*NB*128 + b*128 + tid];
    __syncthreads();

    {
        int w = tid >> 5, lane = tid & 31;
        for (int oo = 0; oo < 32; oo++) {
            int o = w*32 + oo;
            float s = 0.f, c = 0.f;
            #pragma unroll
            for (int j = 0; j < 4; j++) {
                int f = lane + 32*j;
                kfma(s, c, fc1w[o*128 + f], sfeat[f]);
            }
            #pragma unroll
            for (int sh = 16; sh; sh >>= 1) {
                float s2 = __shfl_down_sync(0xffffffffu, s, sh);
                float c2 = __shfl_down_sync(0xffffffffu, c, sh);
                float ttv, ee;
                twoSum(s, s2, ttv, ee);
                c = (c + c2) + ee;
                s = ttv;
            }
            if (lane == 0) sfc1o[o] = s + c;
        }
    }
    __syncthreads();

    {
        float th = thr[2];
        int o = tid;
        float cur = sfc1o[o] + fc1b[o];
        float mem  = g_mem2[b*256 + o];
        float rst  = (mem - th > 0.f) ? 1.f : 0.f;
        float memn = fmaf(0.5f, mem, cur) - rst*th;
        g_mem2[b*256 + o] = memn;
        float spk = (memn - th > 0.f) ? 1.f : 0.f;
        sspk2[o] = spk;
        size_t oi = ((size_t)ts*NB + b)*256 + o;
        out[O_SPK2 + oi] = spk;
        out[O_MEM2 + oi] = memn;
    }
    __syncthreads();

    if (tid < 32) {
        float a0 = 0.f, e0 = 0.f, a1 = 0.f, e1 = 0.f;
        #pragma unroll
        for (int j = 0; j < 8; j++) {
            int o = tid + 32*j;
            float s = sspk2[o];
            kadd(a0, e0, fc2w[o] * s);
            kadd(a1, e1, fc2w[256 + o] * s);
        }
        #pragma unroll
        for (int sh = 16; sh; sh >>= 1) {
            float s2 = __shfl_down_sync(0xffffffffu, a0, sh);
            float c2 = __shfl_down_sync(0xffffffffu, e0, sh);
            float ttv, ee;
            twoSum(a0, s2, ttv, ee);
            e0 = (e0 + c2) + ee; a0 = ttv;
            s2 = __shfl_down_sync(0xffffffffu, a1, sh);
            c2 = __shfl_down_sync(0xffffffffu, e1, sh);
            twoSum(a1, s2, ttv, ee);
            e1 = (e1 + c2) + ee; a1 = ttv;
        }
        if (tid == 0) {
            float th = thr[3];
            float cc[2] = {(a0 + e0) + fc2b[0], (a1 + e1) + fc2b[1]};
            #pragma unroll
            for (int r = 0; r < 2; r++) {
                float mem  = g_mem3[b*2 + r];
                float rst  = (mem - th > 0.f) ? 1.f : 0.f;
                float memn = fmaf(0.5f, mem, cc[r]) - rst*th;
                g_mem3[b*2 + r] = memn;
                float spk = (memn - th > 0.f) ? 1.f : 0.f;
                size_t oi = ((size_t)ts*NB + b)*2 + r;
                out[O_SPK3 + oi] = spk;
                out[O_MEM3 + oi] = memn;
            }
        }
    }
}

// ---- conv2 output at position q via LUT (identical summation order) ----
__device__ __forceinline__ float4 conv_q(const float4* sT,
                                         unsigned m0, unsigned m1, unsigned m2)
{
    float4 acc = make_float4(0.f, 0.f, 0.f, 0.f);
    unsigned mk[3] = {m0, m1, m2};
    #pragma unroll
    for (int k = 0; k < 3; k++) {
        unsigned m = mk[k];
        unsigned v0 = m & 255u, v1 = (m >> 8) & 255u;
        unsigned v2 = (m >> 16) & 255u, v3 = m >> 24;
        const float4* tk = sT + k*4*256;
        float4 l0  = tk[v0];
        float4 l1  = tk[256 + v1];
        float4 l2v = tk[512 + v2];
        float4 l3  = tk[768 + v3];
        acc.x += (l0.x + l1.x) + (l2v.x + l3.x);
        acc.y += (l0.y + l1.y) + (l2v.y + l3.y);
        acc.z += (l0.z + l1.z) + (l2v.z + l3.z);
        acc.w += (l0.w + l1.w) + (l2v.w + l3.w);
    }
    return acc;
}

// ---- LIF1 + output writes + spike-count update for one l2, all 4 oc ----
__device__ __forceinline__ void lif1_emit(
        float4 c0, float4 c1, float4 c2,
        int g, int b, int t, int l, float th,
        float bs0, float bs1, float bs2, float bs3,
        float* cnt0, float* cnt1, float* __restrict__ out)
{
    float cur[4];
    cur[0] = fmaxf(c0.x + bs0, fmaxf(c1.x + bs0, c2.x + bs0));
    cur[1] = fmaxf(c0.y + bs1, fmaxf(c1.y + bs1, c2.y + bs1));
    cur[2] = fmaxf(c0.z + bs2, fmaxf(c1.z + bs2, c2.z + bs2));
    cur[3] = fmaxf(c0.w + bs3, fmaxf(c1.w + bs3, c2.w + bs3));
    #pragma unroll
    for (int o = 0; o < 4; o++) {
        int oc = g*4 + o;
        int sidx = (b*C2 + oc)*L2 + l;
        float mem  = g_mem1[sidx];
        float rst  = (mem - th > 0.f) ? 1.f : 0.f;
        float memn = fmaf(0.5f, mem, cur[o]) - rst*th;
        g_mem1[sidx] = memn;
        float spk = (memn - th > 0.f) ? 1.f : 0.f;
        size_t oi = ((size_t)t*NB + b)*32704 + (size_t)oc*L2 + l;
        out[O_SPK1 + oi] = spk;
        out[O_MEM1 + oi] = memn;
        if (l < 256)  cnt0[o] += spk;
        if (l >= 255) cnt1[o] += spk;
    }
}

// ================= stage2 body: conv2 LUT + maxpool + LIF1 + avgpool counts ==
// one-pass: thread handles l2 = 2*tid and 2*tid+1 (conv positions 4t..4t+4)
__device__ __forceinline__ void stage2_body(
        char* sm, int g, int b, int t,
        const float* __restrict__ b2, const float* __restrict__ thr,
        float* __restrict__ out)
{
    float4*   sT    = (float4*)(sm + SM_T);      // 12*256 float4 = 48KB
    unsigned* smask = (unsigned*)(sm + SM_MASK); // 1032 u32 (halo + zero pad)
    float*    saux  = (float*)(sm + SM_AUX);     // [0:8) counts, [8:12) bias, [12] thr

    int tid = threadIdx.x;
    const unsigned* gm = g_mask[t & 1] + b*L1;

    const float4* lutg = (const float4*)g_lut + (size_t)g*12*256;
    for (int i = tid; i < 12*256; i += 256) sT[i] = lutg[i];
    for (int i = tid; i < 1032; i += 256)
        smask[i] = (i >= 1 && i <= L1) ? gm[i-1] : 0u;
    if (tid < 8) saux[tid] = 0.f;
    if (tid >= 8 && tid < 12) saux[tid] = b2[g*4 + (tid-8)];
    if (tid == 12) saux[12] = thr[1];
    __syncthreads();

    const float th = saux[12];
    const float bs0 = saux[8], bs1 = saux[9], bs2 = saux[10], bs3 = saux[11];
    float cnt0[4] = {0.f,0.f,0.f,0.f}, cnt1[4] = {0.f,0.f,0.f,0.f};

    int q0 = tid*4;
    unsigned mm[7];
    #pragma unroll
    for (int j = 0; j < 7; j++) mm[j] = smask[q0 + j];

    // conv positions q0..q0+4; pool windows share c2
    float4 c0 = conv_q(sT, mm[0], mm[1], mm[2]);
    float4 c1 = conv_q(sT, mm[1], mm[2], mm[3]);
    float4 c2 = conv_q(sT, mm[2], mm[3], mm[4]);
    lif1_emit(c0, c1, c2, g, b, t, 2*tid, th, bs0, bs1, bs2, bs3, cnt0, cnt1, out);

    if (tid < 255) {
        float4 c3 = conv_q(sT, mm[3], mm[4], mm[5]);
        float4 c4 = conv_q(sT, mm[4], mm[5], mm[6]);
        lif1_emit(c2, c3, c4, g, b, t, 2*tid + 1, th, bs0, bs1, bs2, bs3,
                  cnt0, cnt1, out);
    }

    // reduce counts (exact integer sums)
    {
        int lane = tid & 31;
        #pragma unroll
        for (int o = 0; o < 4; o++) {
            float a = cnt0[o], c = cnt1[o];
            #pragma unroll
            for (int sh = 16; sh; sh >>= 1) {
                a += __shfl_down_sync(0xffffffffu, a, sh);
                c += __shfl_down_sync(0xffffffffu, c, sh);
            }
            if (lane == 0) {
                atomicAdd(&saux[o*2 + 0], a);
                atomicAdd(&saux[o*2 + 1], c);
            }
        }
    }
    __syncthreads();
    if (tid < 8)
        g_feat[(size_t)(t&1)*NB*128 + b*128 + g*8 + tid] = saux[tid] * 0.00390625f;
}

// ================= prologue: stage1 for t = 0 =================
__global__ void __launch_bounds__(256) k_pro(
        const float* __restrict__ x, const float* __restrict__ w1,
        const float* __restrict__ b1, const float* __restrict__ thr,
        float* __restrict__ out)
{
    __shared__ float sw[C1*12];
    __shared__ float sb[C1];
    __shared__ float sthr[1];
    stage1_body(sw, sb, sthr, blockIdx.y, blockIdx.x, 0, x, w1, b1, thr, out);
}

// ================= fused: stage2(t) + stage1(t+1) + fc(t-1) =================
// blocks [0,1024): stage2; [1024,1280): stage1(t+1); [1280,1344): fc(t-1)
__global__ void __launch_bounds__(256, 4) k_fused(
        const float* __restrict__ x,
        const float* __restrict__ w1, const float* __restrict__ b1,
        const float* __restrict__ b2,
        const float* __restrict__ fc1w, const float* __restrict__ fc1b,
        const float* __restrict__ fc2w, const float* __restrict__ fc2b,
        const float* __restrict__ thr, float* __restrict__ out, int t)
{
    extern __shared__ char sm[];
    int bid = blockIdx.x;
    if (bid < 1024) {
        stage2_body(sm, bid & 15, bid >> 4, t, b2, thr, out);
    } else if (bid < 1280) {
        if (t + 1 < T_STEPS) {
            int r = bid - 1024;
            float* sw = (float*)sm;
            float* sb = sw + C1*12;
            float* sthr = sb + C1;
            stage1_body(sw, sb, sthr, r >> 2, r & 3, t + 1, x, w1, b1, thr, out);
        }
    } else {
        if (t >= 1)
            fc_block(sm, bid - 1280, t - 1, fc1w, fc1b, fc2w, fc2b, thr, out);
    }
}

// ================= tail: fc for t = 31 =================
__global__ void __launch_bounds__(256) k_tail(
        const float* __restrict__ fc1w, const float* __restrict__ fc1b,
        const float* __restrict__ fc2w, const float* __restrict__ fc2b,
        const float* __restrict__ thr, float* __restrict__ out)
{
    __shared__ char sm[(128 + 256 + 256) * 4];
    fc_block(sm, blockIdx.x, T_STEPS - 1, fc1w, fc1b, fc2w, fc2b, thr, out);
}

extern "C" void kernel_launch(void* const* d_in, const int* in_sizes, int n_in,
                              void* d_out, int out_size)
{
    const float* x   = (const float*)d_in[0];
    const float* c1w = (const float*)d_in[1];
    const float* c1b = (const float*)d_in[2];
    const float* c2w = (const float*)d_in[3];
    const float* c2b = (const float*)d_in[4];
    const float* f1w = (const float*)d_in[5];
    const float* f1b = (const float*)d_in[6];
    const float* f2w = (const float*)d_in[7];
    const float* f2b = (const float*)d_in[8];
    const float* thr = (const float*)d_in[9];
    float* out = (float*)d_out;

    cudaFuncSetAttribute(k_fused, cudaFuncAttributeMaxDynamicSharedMemorySize, SMEM2);

    k_init<<<256, 256>>>();
    k_lut<<<768, 256>>>(c2w);
    k_pro<<<dim3(4, NB), 256>>>(x, c1w, c1b, thr, out);
    for (int t = 0; t < T_STEPS; t++) {
        k_fused<<<1344, 256, SMEM2>>>(x, c1w, c1b, c2b, f1w, f1b, f2w, f2b,
                                      thr, out, t);
    }
    k_tail<<<NB, 256>>>(f1w, f1b, f2w, f2b, thr, out);
}

// round 6
// speedup vs baseline: 1.0589x; 1.0589x over previous
#include <cuda_runtime.h>
#include <cstddef>

#define T_STEPS 32
#define NB      64
#define LEN0    2048
#define L1      1023
#define L2      511
#define C1      32
#define C2      64

// ---- output layout offsets ----
static const size_t O_SPK0 = 0;
static const size_t O_SPK1 = (size_t)T_STEPS*NB*32736;
static const size_t O_SPK2 = O_SPK1 + (size_t)T_STEPS*NB*32704;
static const size_t O_SPK3 = O_SPK2 + (size_t)T_STEPS*NB*256;
static const size_t O_MEM0 = O_SPK3 + (size_t)T_STEPS*NB*2;
static const size_t O_MEM1 = O_MEM0 + (size_t)T_STEPS*NB*32736;
static const size_t O_MEM2 = O_MEM1 + (size_t)T_STEPS*NB*32704;
static const size_t O_MEM3 = O_MEM2 + (size_t)T_STEPS*NB*256;

// ---- persistent state / scratch ----
__device__ float    g_mem0[NB*C1*L1];
__device__ float    g_mem1[NB*C2*L2];
__device__ float    g_mem2[NB*256];
__device__ float    g_mem3[NB*2];
__device__ unsigned g_mask[2][NB*L1];     // double-buffered spike bitmasks
__device__ float    g_feat[2*NB*128];     // double-buffered avgpool features
// LUT: [grp(16)][kb(12)][v(256)] float4 (4 oc per group)
__device__ __align__(16) float g_lut[16*12*256*4];

// smem layout for fused kernel (stage2 role)
#define SM_T    0
#define SM_MASK 49152
#define SM_SWB  (49152 + 4128)      // 8 float4 warp-boundary c0 values
#define SM_AUX  (SM_SWB + 128)
#define SMEM2   (SM_AUX + 64)       // 53,472 bytes -> 4 CTAs/SM

// ================= compensated-arithmetic helpers =================
__device__ __forceinline__ void twoSum(float a, float b, float& s, float& e) {
    s = a + b;
    float bp = s - a;
    float ap = s - bp;
    e = (b - bp) + (a - ap);
}
__device__ __forceinline__ void kadd(float& s, float& c, float v) {
    float t, e;
    twoSum(s, v, t, e);
    c += e;
    s = t;
}
__device__ __forceinline__ void kfma(float& s, float& c, float a, float b) {
    float p = a * b;
    float e = fmaf(a, b, -p);
    kadd(s, c, p);
    c += e;
}

// ================= init: zero membrane states =================
__global__ void k_init() {
    const int n0 = NB*C1*L1, n1 = NB*C2*L2, n2 = NB*256, n3 = NB*2;
    const int n = n0 + n1 + n2 + n3;
    for (int i = blockIdx.x*blockDim.x + threadIdx.x; i < n; i += gridDim.x*blockDim.x) {
        if (i < n0) g_mem0[i] = 0.f;
        else if (i < n0+n1) g_mem1[i-n0] = 0.f;
        else if (i < n0+n1+n2) g_mem2[i-n0-n1] = 0.f;
        else g_mem3[i-n0-n1-n2] = 0.f;
    }
}

// ================= LUT build (double, rounded once) =================
__global__ void k_lut(const float* __restrict__ w2) {
    int i = blockIdx.x*blockDim.x + threadIdx.x;
    if (i >= 16*12*256*4) return;
    int ocl = i & 3;
    int v   = (i >> 2) & 255;
    int tt  = i >> 10;
    int kb  = tt % 12;
    int g   = tt / 12;
    int k   = kb >> 2;
    int b4  = kb & 3;
    int oc  = g*4 + ocl;
    double s = 0.0;
    #pragma unroll
    for (int bit = 0; bit < 8; bit++)
        if ((v >> bit) & 1)
            s += (double)w2[(oc*32 + b4*8 + bit)*3 + k];
    g_lut[i] = (float)s;
}

// ================= stage1 body: conv1 + maxpool + LIF0 =================
__device__ __forceinline__ void stage1_body(
        float* sw, float* sb, float* sthr,
        int b, int tile, int ts,
        const float* __restrict__ x, const float* __restrict__ w1,
        const float* __restrict__ b1, const float* __restrict__ thr,
        float* __restrict__ out)
{
    for (int i = threadIdx.x; i < C1*12; i += 256) sw[i] = w1[i];
    if (threadIdx.x < C1) sb[threadIdx.x] = b1[threadIdx.x];
    if (threadIdx.x == 0) sthr[0] = thr[0];
    __syncthreads();

    int l1 = tile*256 + threadIdx.x;
    if (l1 >= L1) return;

    const float* xb = x + (((size_t)b*T_STEPS + ts)*4)*LEN0;
    float xr[4][5];
    #pragma unroll
    for (int c = 0; c < 4; c++)
        #pragma unroll
        for (int j = 0; j < 5; j++) {
            int gi = 2*l1 - 1 + j;
            xr[c][j] = (gi >= 0 && gi < LEN0) ? xb[c*LEN0 + gi] : 0.f;
        }

    const float th = sthr[0];
    unsigned mask = 0;
    #pragma unroll 2
    for (int oc = 0; oc < C1; oc++) {
        float bb = sb[oc];
        float y0 = bb, y1 = bb, y2 = bb;
        #pragma unroll
        for (int c = 0; c < 4; c++) {
            float w0 = sw[oc*12 + c*3 + 0];
            float w1v = sw[oc*12 + c*3 + 1];
            float w2v = sw[oc*12 + c*3 + 2];
            y0 = fmaf(w0, xr[c][0], fmaf(w1v, xr[c][1], fmaf(w2v, xr[c][2], y0)));
            y1 = fmaf(w0, xr[c][1], fmaf(w1v, xr[c][2], fmaf(w2v, xr[c][3], y1)));
            y2 = fmaf(w0, xr[c][2], fmaf(w1v, xr[c][3], fmaf(w2v, xr[c][4], y2)));
        }
        int dmax = 0;
        float ymax = y0;
        if (y1 > ymax) { ymax = y1; dmax = 1; }
        if (y2 > ymax) { ymax = y2; dmax = 2; }

        float s = bb, cc = 0.f;
        #pragma unroll
        for (int c = 0; c < 4; c++) {
            #pragma unroll
            for (int k = 0; k < 3; k++)
                kfma(s, cc, sw[oc*12 + c*3 + k], xr[c][dmax + k]);
        }
        float cur = s + cc;

        int   sidx = (b*C1 + oc)*L1 + l1;
        float mem  = g_mem0[sidx];
        float rst  = (mem - th > 0.f) ? 1.f : 0.f;
        float memn = fmaf(0.5f, mem, cur) - rst*th;
        g_mem0[sidx] = memn;
        float spk = (memn - th > 0.f) ? 1.f : 0.f;
        if (spk > 0.f) mask |= (1u << oc);
        size_t oi = ((size_t)ts*NB + b)*32736 + (size_t)oc*L1 + l1;
        out[O_SPK0 + oi] = spk;
        out[O_MEM0 + oi] = memn;
    }
    g_mask[ts & 1][b*L1 + l1] = mask;
}

// ================= fc body (fc1 + LIF2 + fc2 + LIF3) for step ts ============
__device__ __forceinline__ void fc_block(
        char* sm, int b, int ts,
        const float* __restrict__ fc1w, const float* __restrict__ fc1b,
        const float* __restrict__ fc2w, const float* __restrict__ fc2b,
        const float* __restrict__ thr, float* __restrict__ out)
{
    float* sfeat = (float*)sm;          // 128
    float* sfc1o = sfeat + 128;         // 256
    float* sspk2 = sfc1o + 256;         // 256
    int tid = threadIdx.x;

    if (tid < 128) sfeat[tid] = g_feat[(size_t)(ts&1)*NB*128 + b*128 + tid];
    __syncthreads();

    {
        int w = tid >> 5, lane = tid & 31;
        for (int oo = 0; oo < 32; oo++) {
            int o = w*32 + oo;
            float s = 0.f, c = 0.f;
            #pragma unroll
            for (int j = 0; j < 4; j++) {
                int f = lane + 32*j;
                kfma(s, c, fc1w[o*128 + f], sfeat[f]);
            }
            #pragma unroll
            for (int sh = 16; sh; sh >>= 1) {
                float s2 = __shfl_down_sync(0xffffffffu, s, sh);
                float c2 = __shfl_down_sync(0xffffffffu, c, sh);
                float ttv, ee;
                twoSum(s, s2, ttv, ee);
                c = (c + c2) + ee;
                s = ttv;
            }
            if (lane == 0) sfc1o[o] = s + c;
        }
    }
    __syncthreads();

    {
        float th = thr[2];
        int o = tid;
        float cur = sfc1o[o] + fc1b[o];
        float mem  = g_mem2[b*256 + o];
        float rst  = (mem - th > 0.f) ? 1.f : 0.f;
        float memn = fmaf(0.5f, mem, cur) - rst*th;
        g_mem2[b*256 + o] = memn;
        float spk = (memn - th > 0.f) ? 1.f : 0.f;
        sspk2[o] = spk;
        size_t oi = ((size_t)ts*NB + b)*256 + o;
        out[O_SPK2 + oi] = spk;
        out[O_MEM2 + oi] = memn;
    }
    __syncthreads();

    if (tid < 32) {
        float a0 = 0.f, e0 = 0.f, a1 = 0.f, e1 = 0.f;
        #pragma unroll
        for (int j = 0; j < 8; j++) {
            int o = tid + 32*j;
            float s = sspk2[o];
            kadd(a0, e0, fc2w[o] * s);
            kadd(a1, e1, fc2w[256 + o] * s);
        }
        #pragma unroll
        for (int sh = 16; sh; sh >>= 1) {
            float s2 = __shfl_down_sync(0xffffffffu, a0, sh);
            float c2 = __shfl_down_sync(0xffffffffu, e0, sh);
            float ttv, ee;
            twoSum(a0, s2, ttv, ee);
            e0 = (e0 + c2) + ee; a0 = ttv;
            s2 = __shfl_down_sync(0xffffffffu, a1, sh);
            c2 = __shfl_down_sync(0xffffffffu, e1, sh);
            twoSum(a1, s2, ttv, ee);
            e1 = (e1 + c2) + ee; a1 = ttv;
        }
        if (tid == 0) {
            float th = thr[3];
            float cc[2] = {(a0 + e0) + fc2b[0], (a1 + e1) + fc2b[1]};
            #pragma unroll
            for (int r = 0; r < 2; r++) {
                float mem  = g_mem3[b*2 + r];
                float rst  = (mem - th > 0.f) ? 1.f : 0.f;
                float memn = fmaf(0.5f, mem, cc[r]) - rst*th;
                g_mem3[b*2 + r] = memn;
                float spk = (memn - th > 0.f) ? 1.f : 0.f;
                size_t oi = ((size_t)ts*NB + b)*2 + r;
                out[O_SPK3 + oi] = spk;
                out[O_MEM3 + oi] = memn;
            }
        }
    }
}

// ---- conv2 output at position q via LUT (identical summation order) ----
__device__ __forceinline__ float4 conv_q(const float4* sT,
                                         unsigned m0, unsigned m1, unsigned m2)
{
    float4 acc = make_float4(0.f, 0.f, 0.f, 0.f);
    unsigned mk[3] = {m0, m1, m2};
    #pragma unroll
    for (int k = 0; k < 3; k++) {
        unsigned m = mk[k];
        unsigned v0 = m & 255u, v1 = (m >> 8) & 255u;
        unsigned v2 = (m >> 16) & 255u, v3 = m >> 24;
        const float4* tk = sT + k*4*256;
        float4 l0  = tk[v0];
        float4 l1  = tk[256 + v1];
        float4 l2v = tk[512 + v2];
        float4 l3  = tk[768 + v3];
        acc.x += (l0.x + l1.x) + (l2v.x + l3.x);
        acc.y += (l0.y + l1.y) + (l2v.y + l3.y);
        acc.z += (l0.z + l1.z) + (l2v.z + l3.z);
        acc.w += (l0.w + l1.w) + (l2v.w + l3.w);
    }
    return acc;
}

// ---- LIF1 + output writes + spike-count update for one l2, all 4 oc ----
__device__ __forceinline__ void lif1_emit(
        float4 c0, float4 c1, float4 c2,
        int g, int b, int t, int l, float th,
        float bs0, float bs1, float bs2, float bs3,
        float* cnt0, float* cnt1, float* __restrict__ out)
{
    float cur[4];
    cur[0] = fmaxf(c0.x + bs0, fmaxf(c1.x + bs0, c2.x + bs0));
    cur[1] = fmaxf(c0.y + bs1, fmaxf(c1.y + bs1, c2.y + bs1));
    cur[2] = fmaxf(c0.z + bs2, fmaxf(c1.z + bs2, c2.z + bs2));
    cur[3] = fmaxf(c0.w + bs3, fmaxf(c1.w + bs3, c2.w + bs3));
    #pragma unroll
    for (int o = 0; o < 4; o++) {
        int oc = g*4 + o;
        int sidx = (b*C2 + oc)*L2 + l;
        float mem  = g_mem1[sidx];
        float rst  = (mem - th > 0.f) ? 1.f : 0.f;
        float memn = fmaf(0.5f, mem, cur[o]) - rst*th;
        g_mem1[sidx] = memn;
        float spk = (memn - th > 0.f) ? 1.f : 0.f;
        size_t oi = ((size_t)t*NB + b)*32704 + (size_t)oc*L2 + l;
        out[O_SPK1 + oi] = spk;
        out[O_MEM1 + oi] = memn;
        if (l < 256)  cnt0[o] += spk;
        if (l >= 255) cnt1[o] += spk;
    }
}

// ================= stage2 body: conv2 LUT + maxpool + LIF1 + avgpool counts ==
// thread computes conv q=4t..4t+3 in registers; c4 via shfl/warp-boundary smem
__device__ __forceinline__ void stage2_body(
        char* sm, int g, int b, int t,
        const float* __restrict__ b2, const float* __restrict__ thr,
        float* __restrict__ out)
{
    float4*   sT    = (float4*)(sm + SM_T);      // 12*256 float4 = 48KB
    unsigned* smask = (unsigned*)(sm + SM_MASK); // 1032 u32 (halo + zero pad)
    float4*   swb   = (float4*)(sm + SM_SWB);    // 8 warp-boundary c0 values
    float*    saux  = (float*)(sm + SM_AUX);     // counts/bias/thr

    int tid = threadIdx.x;
    const unsigned* gm = g_mask[t & 1] + b*L1;

    const float4* lutg = (const float4*)g_lut + (size_t)g*12*256;
    for (int i = tid; i < 12*256; i += 256) sT[i] = lutg[i];
    for (int i = tid; i < 1032; i += 256)
        smask[i] = (i >= 1 && i <= L1) ? gm[i-1] : 0u;
    if (tid < 8) saux[tid] = 0.f;
    if (tid >= 8 && tid < 12) saux[tid] = b2[g*4 + (tid-8)];
    if (tid == 12) saux[12] = thr[1];
    __syncthreads();

    const float th = saux[12];
    const float bs0 = saux[8], bs1 = saux[9], bs2 = saux[10], bs3 = saux[11];
    float cnt0[4] = {0.f,0.f,0.f,0.f}, cnt1[4] = {0.f,0.f,0.f,0.f};

    int q0 = tid*4;
    unsigned mm[6];
    #pragma unroll
    for (int j = 0; j < 6; j++) mm[j] = smask[q0 + j];

    int lane = tid & 31;
    int w    = tid >> 5;

    // c0 first, then exchange it to neighbours
    float4 c0 = conv_q(sT, mm[0], mm[1], mm[2]);
    float4 c4;
    c4.x = __shfl_down_sync(0xffffffffu, c0.x, 1);
    c4.y = __shfl_down_sync(0xffffffffu, c0.y, 1);
    c4.z = __shfl_down_sync(0xffffffffu, c0.z, 1);
    c4.w = __shfl_down_sync(0xffffffffu, c0.w, 1);
    if (lane == 0) swb[w] = c0;
    __syncthreads();
    if (lane == 31 && w < 7) c4 = swb[w + 1];

    // l2 = 2*tid (conv q0, q0+1, q0+2)
    {
        float4 c1 = conv_q(sT, mm[1], mm[2], mm[3]);
        float4 c2 = conv_q(sT, mm[2], mm[3], mm[4]);
        lif1_emit(c0, c1, c2, g, b, t, 2*tid, th, bs0, bs1, bs2, bs3,
                  cnt0, cnt1, out);
        // l2 = 2*tid+1 (conv q0+2, q0+3, q0+4)
        if (tid < 255) {
            float4 c3 = conv_q(sT, mm[3], mm[4], mm[5]);
            lif1_emit(c2, c3, c4, g, b, t, 2*tid + 1, th, bs0, bs1, bs2, bs3,
                      cnt0, cnt1, out);
        }
    }

    // reduce counts (exact integer sums)
    #pragma unroll
    for (int o = 0; o < 4; o++) {
        float a = cnt0[o], c = cnt1[o];
        #pragma unroll
        for (int sh = 16; sh; sh >>= 1) {
            a += __shfl_down_sync(0xffffffffu, a, sh);
            c += __shfl_down_sync(0xffffffffu, c, sh);
        }
        if (lane == 0) {
            atomicAdd(&saux[o*2 + 0], a);
            atomicAdd(&saux[o*2 + 1], c);
        }
    }
    __syncthreads();
    if (tid < 8)
        g_feat[(size_t)(t&1)*NB*128 + b*128 + g*8 + tid] = saux[tid] * 0.00390625f;
}

// ================= prologue: stage1 for t = 0 =================
__global__ void __launch_bounds__(256) k_pro(
        const float* __restrict__ x, const float* __restrict__ w1,
        const float* __restrict__ b1, const float* __restrict__ thr,
        float* __restrict__ out)
{
    __shared__ float sw[C1*12];
    __shared__ float sb[C1];
    __shared__ float sthr[1];
    stage1_body(sw, sb, sthr, blockIdx.y, blockIdx.x, 0, x, w1, b1, thr, out);
}

// ================= fused: stage2(t) + stage1(t+1) + fc(t-1) =================
// blocks [0,1024): stage2; [1024,1280): stage1(t+1); [1280,1344): fc(t-1)
__global__ void __launch_bounds__(256, 4) k_fused(
        const float* __restrict__ x,
        const float* __restrict__ w1, const float* __restrict__ b1,
        const float* __restrict__ b2,
        const float* __restrict__ fc1w, const float* __restrict__ fc1b,
        const float* __restrict__ fc2w, const float* __restrict__ fc2b,
        const float* __restrict__ thr, float* __restrict__ out, int t)
{
    extern __shared__ char sm[];
    int bid = blockIdx.x;
    if (bid < 1024) {
        stage2_body(sm, bid & 15, bid >> 4, t, b2, thr, out);
    } else if (bid < 1280) {
        if (t + 1 < T_STEPS) {
            int r = bid - 1024;
            float* sw = (float*)sm;
            float* sb = sw + C1*12;
            float* sthr = sb + C1;
            stage1_body(sw, sb, sthr, r >> 2, r & 3, t + 1, x, w1, b1, thr, out);
        }
    } else {
        if (t >= 1)
            fc_block(sm, bid - 1280, t - 1, fc1w, fc1b, fc2w, fc2b, thr, out);
    }
}

// ================= tail: fc for t = 31 =================
__global__ void __launch_bounds__(256) k_tail(
        const float* __restrict__ fc1w, const float* __restrict__ fc1b,
        const float* __restrict__ fc2w, const float* __restrict__ fc2b,
        const float* __restrict__ thr, float* __restrict__ out)
{
    __shared__ char sm[(128 + 256 + 256) * 4];
    fc_block(sm, blockIdx.x, T_STEPS - 1, fc1w, fc1b, fc2w, fc2b, thr, out);
}

extern "C" void kernel_launch(void* const* d_in, const int* in_sizes, int n_in,
                              void* d_out, int out_size)
{
    const float* x   = (const float*)d_in[0];
    const float* c1w = (const float*)d_in[1];
    const float* c1b = (const float*)d_in[2];
    const float* c2w = (const float*)d_in[3];
    const float* c2b = (const float*)d_in[4];
    const float* f1w = (const float*)d_in[5];
    const float* f1b = (const float*)d_in[6];
    const float* f2w = (const float*)d_in[7];
    const float* f2b = (const float*)d_in[8];
    const float* thr = (const float*)d_in[9];
    float* out = (float*)d_out;

    cudaFuncSetAttribute(k_fused, cudaFuncAttributeMaxDynamicSharedMemorySize, SMEM2);

    k_init<<<256, 256>>>();
    k_lut<<<768, 256>>>(c2w);
    k_pro<<<dim3(4, NB), 256>>>(x, c1w, c1b, thr, out);
    for (int t = 0; t < T_STEPS; t++) {
        k_fused<<<1344, 256, SMEM2>>>(x, c1w, c1b, c2b, f1w, f1b, f2w, f2b,
                                      thr, out, t);
    }
    k_tail<<<NB, 256>>>(f1w, f1b, f2w, f2b, thr, out);
}

// round 7
// speedup vs baseline: 1.2394x; 1.1704x over previous
#include <cuda_runtime.h>
#include <cstddef>

#define T_STEPS 32
#define NB      64
#define LEN0    2048
#define L1      1023
#define L2      511
#define C1      32
#define C2      64

// ---- output layout offsets ----
static const size_t O_SPK0 = 0;
static const size_t O_SPK1 = (size_t)T_STEPS*NB*32736;
static const size_t O_SPK2 = O_SPK1 + (size_t)T_STEPS*NB*32704;
static const size_t O_SPK3 = O_SPK2 + (size_t)T_STEPS*NB*256;
static const size_t O_MEM0 = O_SPK3 + (size_t)T_STEPS*NB*2;
static const size_t O_MEM1 = O_MEM0 + (size_t)T_STEPS*NB*32736;
static const size_t O_MEM2 = O_MEM1 + (size_t)T_STEPS*NB*32704;
static const size_t O_MEM3 = O_MEM2 + (size_t)T_STEPS*NB*256;

// ---- persistent state / scratch ----
__device__ float    g_mem0[NB*C1*L1];
__device__ float    g_mem1[NB*C2*L2];
__device__ float    g_mem2[NB*256];
__device__ float    g_mem3[NB*2];
__device__ unsigned g_mask[2][NB*L1];     // double-buffered spike bitmasks
__device__ float    g_feat[2*NB*128];     // double-buffered avgpool features
// LUT: [grp(16)][kb(12)][v(256)] float4 (4 oc per group)
__device__ __align__(16) float g_lut[16*12*256*4];

// smem layout for fused kernel (stage2 role): LUT + masks + sc staging + aux
#define SM_T    0
#define SM_MASK 49152
#define SM_SC   (49152 + 4128)
#define SM_AUX  (SM_SC + 16368)
#define SMEM2   (SM_AUX + 64)     // 69,712 bytes -> 3 CTAs/SM

// ================= compensated-arithmetic helpers =================
__device__ __forceinline__ void twoSum(float a, float b, float& s, float& e) {
    s = a + b;
    float bp = s - a;
    float ap = s - bp;
    e = (b - bp) + (a - ap);
}
__device__ __forceinline__ void kadd(float& s, float& c, float v) {
    float t, e;
    twoSum(s, v, t, e);
    c += e;
    s = t;
}
__device__ __forceinline__ void kfma(float& s, float& c, float a, float b) {
    float p = a * b;
    float e = fmaf(a, b, -p);
    kadd(s, c, p);
    c += e;
}

// ================= init: zero membrane states =================
__global__ void k_init() {
    const int n0 = NB*C1*L1, n1 = NB*C2*L2, n2 = NB*256, n3 = NB*2;
    const int n = n0 + n1 + n2 + n3;
    for (int i = blockIdx.x*blockDim.x + threadIdx.x; i < n; i += gridDim.x*blockDim.x) {
        if (i < n0) g_mem0[i] = 0.f;
        else if (i < n0+n1) g_mem1[i-n0] = 0.f;
        else if (i < n0+n1+n2) g_mem2[i-n0-n1] = 0.f;
        else g_mem3[i-n0-n1-n2] = 0.f;
    }
}

// ================= LUT build (double, rounded once) =================
__global__ void k_lut(const float* __restrict__ w2) {
    int i = blockIdx.x*blockDim.x + threadIdx.x;
    if (i >= 16*12*256*4) return;
    int ocl = i & 3;
    int v   = (i >> 2) & 255;
    int tt  = i >> 10;
    int kb  = tt % 12;
    int g   = tt / 12;
    int k   = kb >> 2;
    int b4  = kb & 3;
    int oc  = g*4 + ocl;
    double s = 0.0;
    #pragma unroll
    for (int bit = 0; bit < 8; bit++)
        if ((v >> bit) & 1)
            s += (double)w2[(oc*32 + b4*8 + bit)*3 + k];
    g_lut[i] = (float)s;
}

// ================= stage1 body: conv1 + maxpool + LIF0 =================
__device__ __forceinline__ void stage1_body(
        float* sw, float* sb, float* sthr,
        int b, int tile, int ts,
        const float* __restrict__ x, const float* __restrict__ w1,
        const float* __restrict__ b1, const float* __restrict__ thr,
        float* __restrict__ out)
{
    for (int i = threadIdx.x; i < C1*12; i += 256) sw[i] = w1[i];
    if (threadIdx.x < C1) sb[threadIdx.x] = b1[threadIdx.x];
    if (threadIdx.x == 0) sthr[0] = thr[0];
    __syncthreads();

    int l1 = tile*256 + threadIdx.x;
    if (l1 >= L1) return;

    const float* xb = x + (((size_t)b*T_STEPS + ts)*4)*LEN0;
    float xr[4][5];
    #pragma unroll
    for (int c = 0; c < 4; c++)
        #pragma unroll
        for (int j = 0; j < 5; j++) {
            int gi = 2*l1 - 1 + j;
            xr[c][j] = (gi >= 0 && gi < LEN0) ? xb[c*LEN0 + gi] : 0.f;
        }

    const float th = sthr[0];
    unsigned mask = 0;
    #pragma unroll 2
    for (int oc = 0; oc < C1; oc++) {
        float bb = sb[oc];
        float y0 = bb, y1 = bb, y2 = bb;
        #pragma unroll
        for (int c = 0; c < 4; c++) {
            float w0 = sw[oc*12 + c*3 + 0];
            float w1v = sw[oc*12 + c*3 + 1];
            float w2v = sw[oc*12 + c*3 + 2];
            y0 = fmaf(w0, xr[c][0], fmaf(w1v, xr[c][1], fmaf(w2v, xr[c][2], y0)));
            y1 = fmaf(w0, xr[c][1], fmaf(w1v, xr[c][2], fmaf(w2v, xr[c][3], y1)));
            y2 = fmaf(w0, xr[c][2], fmaf(w1v, xr[c][3], fmaf(w2v, xr[c][4], y2)));
        }
        int dmax = 0;
        float ymax = y0;
        if (y1 > ymax) { ymax = y1; dmax = 1; }
        if (y2 > ymax) { ymax = y2; dmax = 2; }

        float s = bb, cc = 0.f;
        #pragma unroll
        for (int c = 0; c < 4; c++) {
            #pragma unroll
            for (int k = 0; k < 3; k++)
                kfma(s, cc, sw[oc*12 + c*3 + k], xr[c][dmax + k]);
        }
        float cur = s + cc;

        int   sidx = (b*C1 + oc)*L1 + l1;
        float mem  = g_mem0[sidx];
        float rst  = (mem - th > 0.f) ? 1.f : 0.f;
        float memn = fmaf(0.5f, mem, cur) - rst*th;
        g_mem0[sidx] = memn;
        float spk = (memn - th > 0.f) ? 1.f : 0.f;
        if (spk > 0.f) mask |= (1u << oc);
        size_t oi = ((size_t)ts*NB + b)*32736 + (size_t)oc*L1 + l1;
        out[O_SPK0 + oi] = spk;
        out[O_MEM0 + oi] = memn;
    }
    g_mask[ts & 1][b*L1 + l1] = mask;
}

// ================= fc body (fc1 + LIF2 + fc2 + LIF3) for step ts ============
__device__ __forceinline__ void fc_block(
        char* sm, int b, int ts,
        const float* __restrict__ fc1w, const float* __restrict__ fc1b,
        const float* __restrict__ fc2w, const float* __restrict__ fc2b,
        const float* __restrict__ thr, float* __restrict__ out)
{
    float* sfeat = (float*)sm;          // 128
    float* sfc1o = sfeat + 128;         // 256
    float* sspk2 = sfc1o + 256;         // 256
    int tid = threadIdx.x;

    if (tid < 128) sfeat[tid] = g_feat[(size_t)(ts&1)*NB*128 + b*128 + tid];
    __syncthreads();

    {
        int w = tid >> 5, lane = tid & 31;
        for (int oo = 0; oo < 32; oo++) {
            int o = w*32 + oo;
            float s = 0.f, c = 0.f;
            #pragma unroll
            for (int j = 0; j < 4; j++) {
                int f = lane + 32*j;
                kfma(s, c, fc1w[o*128 + f], sfeat[f]);
            }
            #pragma unroll
            for (int sh = 16; sh; sh >>= 1) {
                float s2 = __shfl_down_sync(0xffffffffu, s, sh);
                float c2 = __shfl_down_sync(0xffffffffu, c, sh);
                float ttv, ee;
                twoSum(s, s2, ttv, ee);
                c = (c + c2) + ee;
                s = ttv;
            }
            if (lane == 0) sfc1o[o] = s + c;
        }
    }
    __syncthreads();

    {
        float th = thr[2];
        int o = tid;
        float cur = sfc1o[o] + fc1b[o];
        float mem  = g_mem2[b*256 + o];
        float rst  = (mem - th > 0.f) ? 1.f : 0.f;
        float memn = fmaf(0.5f, mem, cur) - rst*th;
        g_mem2[b*256 + o] = memn;
        float spk = (memn - th > 0.f) ? 1.f : 0.f;
        sspk2[o] = spk;
        size_t oi = ((size_t)ts*NB + b)*256 + o;
        out[O_SPK2 + oi] = spk;
        out[O_MEM2 + oi] = memn;
    }
    __syncthreads();

    if (tid < 32) {
        float a0 = 0.f, e0 = 0.f, a1 = 0.f, e1 = 0.f;
        #pragma unroll
        for (int j = 0; j < 8; j++) {
            int o = tid + 32*j;
            float s = sspk2[o];
            kadd(a0, e0, fc2w[o] * s);
            kadd(a1, e1, fc2w[256 + o] * s);
        }
        #pragma unroll
        for (int sh = 16; sh; sh >>= 1) {
            float s2 = __shfl_down_sync(0xffffffffu, a0, sh);
            float c2 = __shfl_down_sync(0xffffffffu, e0, sh);
            float ttv, ee;
            twoSum(a0, s2, ttv, ee);
            e0 = (e0 + c2) + ee; a0 = ttv;
            s2 = __shfl_down_sync(0xffffffffu, a1, sh);
            c2 = __shfl_down_sync(0xffffffffu, e1, sh);
            twoSum(a1, s2, ttv, ee);
            e1 = (e1 + c2) + ee; a1 = ttv;
        }
        if (tid == 0) {
            float th = thr[3];
            float cc[2] = {(a0 + e0) + fc2b[0], (a1 + e1) + fc2b[1]};
            #pragma unroll
            for (int r = 0; r < 2; r++) {
                float mem  = g_mem3[b*2 + r];
                float rst  = (mem - th > 0.f) ? 1.f : 0.f;
                float memn = fmaf(0.5f, mem, cc[r]) - rst*th;
                g_mem3[b*2 + r] = memn;
                float spk = (memn - th > 0.f) ? 1.f : 0.f;
                size_t oi = ((size_t)ts*NB + b)*2 + r;
                out[O_SPK3 + oi] = spk;
                out[O_MEM3 + oi] = memn;
            }
        }
    }
}

// ================= stage2 for one batch (LUT already resident in smem) ======
__device__ __forceinline__ void stage2_batch(
        const float4* sT, unsigned* smask, float4* sc, float* saux,
        int g, int b, int t,
        const float* __restrict__ b2, const float* __restrict__ thr,
        float* __restrict__ out)
{
    int tid = threadIdx.x;
    const unsigned* gm = g_mask[t & 1] + b*L1;

    for (int i = tid; i < 1032; i += 256)
        smask[i] = (i >= 1 && i <= L1) ? gm[i-1] : 0u;
    if (tid < 8) saux[tid] = 0.f;
    if (tid >= 8 && tid < 12) saux[tid] = b2[g*4 + (tid-8)];
    if (tid == 12) saux[12] = thr[1];
    __syncthreads();

    // pass A: conv outputs into sc (zero-byte lookups skipped; exact +0)
    {
        int q0 = tid*4;
        unsigned mm[6];
        #pragma unroll
        for (int j = 0; j < 6; j++) mm[j] = smask[q0 + j];
        #pragma unroll
        for (int i = 0; i < 4; i++) {
            int q = q0 + i;
            if (q < L1) {
                float4 acc = make_float4(0.f, 0.f, 0.f, 0.f);
                #pragma unroll
                for (int k = 0; k < 3; k++) {
                    unsigned m = mm[i + k];
                    unsigned v0 = m & 255u, v1 = (m >> 8) & 255u;
                    unsigned v2 = (m >> 16) & 255u, v3 = m >> 24;
                    const float4* tk = sT + k*4*256;
                    float4 l0 = make_float4(0.f,0.f,0.f,0.f);
                    float4 l1 = l0, l2v = l0, l3 = l0;
                    if (v0) l0  = tk[v0];
                    if (v1) l1  = tk[256 + v1];
                    if (v2) l2v = tk[512 + v2];
                    if (v3) l3  = tk[768 + v3];
                    acc.x += (l0.x + l1.x) + (l2v.x + l3.x);
                    acc.y += (l0.y + l1.y) + (l2v.y + l3.y);
                    acc.z += (l0.z + l1.z) + (l2v.z + l3.z);
                    acc.w += (l0.w + l1.w) + (l2v.w + l3.w);
                }
                sc[q] = acc;
            }
        }
    }
    __syncthreads();

    // pass B: maxpool + LIF1 + writes + spike counts
    const float th = saux[12];
    const float bs0 = saux[8], bs1 = saux[9], bs2 = saux[10], bs3 = saux[11];
    float cnt0[4] = {0.f,0.f,0.f,0.f}, cnt1[4] = {0.f,0.f,0.f,0.f};

    for (int l = tid; l < L2; l += 256) {
        float4 c0 = sc[2*l], c1 = sc[2*l + 1], c2 = sc[2*l + 2];
        float cur[4];
        cur[0] = fmaxf(c0.x + bs0, fmaxf(c1.x + bs0, c2.x + bs0));
        cur[1] = fmaxf(c0.y + bs1, fmaxf(c1.y + bs1, c2.y + bs1));
        cur[2] = fmaxf(c0.z + bs2, fmaxf(c1.z + bs2, c2.z + bs2));
        cur[3] = fmaxf(c0.w + bs3, fmaxf(c1.w + bs3, c2.w + bs3));
        #pragma unroll
        for (int o = 0; o < 4; o++) {
            int oc = g*4 + o;
            int sidx = (b*C2 + oc)*L2 + l;
            float mem  = g_mem1[sidx];
            float rst  = (mem - th > 0.f) ? 1.f : 0.f;
            float memn = fmaf(0.5f, mem, cur[o]) - rst*th;
            g_mem1[sidx] = memn;
            float spk = (memn - th > 0.f) ? 1.f : 0.f;
            size_t oi = ((size_t)t*NB + b)*32704 + (size_t)oc*L2 + l;
            out[O_SPK1 + oi] = spk;
            out[O_MEM1 + oi] = memn;
            if (l < 256)  cnt0[o] += spk;
            if (l >= 255) cnt1[o] += spk;
        }
    }

    {
        int lane = tid & 31;
        #pragma unroll
        for (int o = 0; o < 4; o++) {
            float a = cnt0[o], c = cnt1[o];
            #pragma unroll
            for (int sh = 16; sh; sh >>= 1) {
                a += __shfl_down_sync(0xffffffffu, a, sh);
                c += __shfl_down_sync(0xffffffffu, c, sh);
            }
            if (lane == 0) {
                atomicAdd(&saux[o*2 + 0], a);
                atomicAdd(&saux[o*2 + 1], c);
            }
        }
    }
    __syncthreads();
    if (tid < 8)
        g_feat[(size_t)(t&1)*NB*128 + b*128 + g*8 + tid] = saux[tid] * 0.00390625f;
}

// ================= stage2 block: LUT loaded once, two batches processed =====
__device__ __forceinline__ void stage2_body2(
        char* sm, int g, int bpair, int t,
        const float* __restrict__ b2, const float* __restrict__ thr,
        float* __restrict__ out)
{
    float4*   sT    = (float4*)(sm + SM_T);      // 12*256 float4 = 48KB
    unsigned* smask = (unsigned*)(sm + SM_MASK); // 1032 u32
    float4*   sc    = (float4*)(sm + SM_SC);     // 1023 float4
    float*    saux  = (float*)(sm + SM_AUX);

    int tid = threadIdx.x;
    const float4* lutg = (const float4*)g_lut + (size_t)g*12*256;
    for (int i = tid; i < 12*256; i += 256) sT[i] = lutg[i];
    // (mask load for batch 0 syncs before use inside stage2_batch)

    stage2_batch(sT, smask, sc, saux, g, 2*bpair + 0, t, b2, thr, out);
    __syncthreads();   // drain batch-0 use of smask/sc/saux before reuse
    stage2_batch(sT, smask, sc, saux, g, 2*bpair + 1, t, b2, thr, out);
}

// ================= prologue: stage1 for t = 0 =================
__global__ void __launch_bounds__(256) k_pro(
        const float* __restrict__ x, const float* __restrict__ w1,
        const float* __restrict__ b1, const float* __restrict__ thr,
        float* __restrict__ out)
{
    __shared__ float sw[C1*12];
    __shared__ float sb[C1];
    __shared__ float sthr[1];
    stage1_body(sw, sb, sthr, blockIdx.y, blockIdx.x, 0, x, w1, b1, thr, out);
}

// ================= fused: stage2(t) + stage1(t+1) + fc(t-1) =================
// blocks [0,512): stage2 (16 g x 32 batch-pairs); [512,768): stage1(t+1);
// [768,832): fc(t-1)
__global__ void __launch_bounds__(256, 3) k_fused(
        const float* __restrict__ x,
        const float* __restrict__ w1, const float* __restrict__ b1,
        const float* __restrict__ b2,
        const float* __restrict__ fc1w, const float* __restrict__ fc1b,
        const float* __restrict__ fc2w, const float* __restrict__ fc2b,
        const float* __restrict__ thr, float* __restrict__ out, int t)
{
    extern __shared__ char sm[];
    int bid = blockIdx.x;
    if (bid < 512) {
        stage2_body2(sm, bid & 15, bid >> 4, t, b2, thr, out);
    } else if (bid < 768) {
        if (t + 1 < T_STEPS) {
            int r = bid - 512;
            float* sw = (float*)sm;
            float* sb = sw + C1*12;
            float* sthr = sb + C1;
            stage1_body(sw, sb, sthr, r >> 2, r & 3, t + 1, x, w1, b1, thr, out);
        }
    } else {
        if (t >= 1)
            fc_block(sm, bid - 768, t - 1, fc1w, fc1b, fc2w, fc2b, thr, out);
    }
}

// ================= tail: fc for t = 31 =================
__global__ void __launch_bounds__(256) k_tail(
        const float* __restrict__ fc1w, const float* __restrict__ fc1b,
        const float* __restrict__ fc2w, const float* __restrict__ fc2b,
        const float* __restrict__ thr, float* __restrict__ out)
{
    __shared__ char sm[(128 + 256 + 256) * 4];
    fc_block(sm, blockIdx.x, T_STEPS - 1, fc1w, fc1b, fc2w, fc2b, thr, out);
}

extern "C" void kernel_launch(void* const* d_in, const int* in_sizes, int n_in,
                              void* d_out, int out_size)
{
    const float* x   = (const float*)d_in[0];
    const float* c1w = (const float*)d_in[1];
    const float* c1b = (const float*)d_in[2];
    const float* c2w = (const float*)d_in[3];
    const float* c2b = (const float*)d_in[4];
    const float* f1w = (const float*)d_in[5];
    const float* f1b = (const float*)d_in[6];
    const float* f2w = (const float*)d_in[7];
    const float* f2b = (const float*)d_in[8];
    const float* thr = (const float*)d_in[9];
    float* out = (float*)d_out;

    cudaFuncSetAttribute(k_fused, cudaFuncAttributeMaxDynamicSharedMemorySize, SMEM2);

    k_init<<<256, 256>>>();
    k_lut<<<768, 256>>>(c2w);
    k_pro<<<dim3(4, NB), 256>>>(x, c1w, c1b, thr, out);
    for (int t = 0; t < T_STEPS; t++) {
        k_fused<<<832, 256, SMEM2>>>(x, c1w, c1b, c2b, f1w, f1b, f2w, f2b,
                                     thr, out, t);
    }
    k_tail<<<NB, 256>>>(f1w, f1b, f2w, f2b, thr, out);
}

// round 8
// speedup vs baseline: 1.2441x; 1.0038x over previous
#include <cuda_runtime.h>
#include <cstddef>

#define T_STEPS 32
#define NB      64
#define LEN0    2048
#define L1      1023
#define L2      511
#define C1      32
#define C2      64

// ---- output layout offsets ----
static const size_t O_SPK0 = 0;
static const size_t O_SPK1 = (size_t)T_STEPS*NB*32736;
static const size_t O_SPK2 = O_SPK1 + (size_t)T_STEPS*NB*32704;
static const size_t O_SPK3 = O_SPK2 + (size_t)T_STEPS*NB*256;
static const size_t O_MEM0 = O_SPK3 + (size_t)T_STEPS*NB*2;
static const size_t O_MEM1 = O_MEM0 + (size_t)T_STEPS*NB*32736;
static const size_t O_MEM2 = O_MEM1 + (size_t)T_STEPS*NB*32704;
static const size_t O_MEM3 = O_MEM2 + (size_t)T_STEPS*NB*256;

// ---- persistent state / scratch ----
__device__ float    g_mem0[NB*C1*L1];
__device__ float    g_mem1[NB*C2*L2];
__device__ float    g_mem2[NB*256];
__device__ float    g_mem3[NB*2];
__device__ unsigned g_mask[2][NB*L1];
__device__ float    g_feat[2*NB*128];
// LUT: [grp(16)][kb(12)][v(256)] float4 (4 oc per group)
__device__ __align__(16) float g_lut[16*12*256*4];

// smem layout for fused kernel (stage2 role)
#define SM_T    0
#define SM_MASK 49152
#define SM_SC   (49152 + 4128)
#define SM_AUX  (SM_SC + 16368)
#define SMEM2   (SM_AUX + 64)     // 69,712 bytes -> 3 CTAs/SM

typedef unsigned long long u64;

// ================= packed f32x2 helpers (bit-identical per-lane rounding) ====
__device__ __forceinline__ u64 PK(float lo, float hi) {
    u64 r; asm("mov.b64 %0,{%1,%2};" : "=l"(r) : "f"(lo), "f"(hi)); return r;
}
__device__ __forceinline__ void UPK(u64 v, float& lo, float& hi) {
    asm("mov.b64 {%0,%1},%2;" : "=f"(lo), "=f"(hi) : "l"(v));
}
__device__ __forceinline__ u64 FMA2(u64 a, u64 b, u64 c) {
    u64 d; asm("fma.rn.f32x2 %0,%1,%2,%3;" : "=l"(d) : "l"(a), "l"(b), "l"(c)); return d;
}
__device__ __forceinline__ u64 ADD2(u64 a, u64 b) {
    u64 d; asm("add.rn.f32x2 %0,%1,%2;" : "=l"(d) : "l"(a), "l"(b)); return d;
}
__device__ __forceinline__ u64 MUL2(u64 a, u64 b) {
    u64 d; asm("mul.rn.f32x2 %0,%1,%2;" : "=l"(d) : "l"(a), "l"(b)); return d;
}
__device__ __forceinline__ u64 NEG2(u64 a) { return a ^ 0x8000000080000000ULL; }

__device__ __forceinline__ void twoSum2(u64 a, u64 b, u64& s, u64& e) {
    s = ADD2(a, b);
    u64 bp = ADD2(s, NEG2(a));
    u64 ap = ADD2(s, NEG2(bp));
    e = ADD2(ADD2(b, NEG2(bp)), ADD2(a, NEG2(ap)));
}
// packed kfma: identical op order to scalar kfma per lane
__device__ __forceinline__ void kfma2(u64& s, u64& c, u64 a, u64 b) {
    u64 p = MUL2(a, b);
    u64 e = FMA2(a, b, NEG2(p));
    u64 t, e2;
    twoSum2(s, p, t, e2);
    c = ADD2(c, e2);
    s = t;
    c = ADD2(c, e);
}

// ================= scalar compensated helpers (fc path) =================
__device__ __forceinline__ void twoSum(float a, float b, float& s, float& e) {
    s = a + b;
    float bp = s - a;
    float ap = s - bp;
    e = (b - bp) + (a - ap);
}
__device__ __forceinline__ void kadd(float& s, float& c, float v) {
    float t, e;
    twoSum(s, v, t, e);
    c += e;
    s = t;
}
__device__ __forceinline__ void kfma(float& s, float& c, float a, float b) {
    float p = a * b;
    float e = fmaf(a, b, -p);
    kadd(s, c, p);
    c += e;
}

// ================= init: zero membrane states =================
__global__ void k_init() {
    const int n0 = NB*C1*L1, n1 = NB*C2*L2, n2 = NB*256, n3 = NB*2;
    const int n = n0 + n1 + n2 + n3;
    for (int i = blockIdx.x*blockDim.x + threadIdx.x; i < n; i += gridDim.x*blockDim.x) {
        if (i < n0) g_mem0[i] = 0.f;
        else if (i < n0+n1) g_mem1[i-n0] = 0.f;
        else if (i < n0+n1+n2) g_mem2[i-n0-n1] = 0.f;
        else g_mem3[i-n0-n1-n2] = 0.f;
    }
}

// ================= LUT build (double, rounded once) =================
__global__ void k_lut(const float* __restrict__ w2) {
    int i = blockIdx.x*blockDim.x + threadIdx.x;
    if (i >= 16*12*256*4) return;
    int ocl = i & 3;
    int v   = (i >> 2) & 255;
    int tt  = i >> 10;
    int kb  = tt % 12;
    int g   = tt / 12;
    int k   = kb >> 2;
    int b4  = kb & 3;
    int oc  = g*4 + ocl;
    double s = 0.0;
    #pragma unroll
    for (int bit = 0; bit < 8; bit++)
        if ((v >> bit) & 1)
            s += (double)w2[(oc*32 + b4*8 + bit)*3 + k];
    g_lut[i] = (float)s;
}

// ================= stage1 body: conv1 + maxpool + LIF0 (f32x2 packed) =======
// swp: float2[16*12] packed weight pairs; sbp: float2[16] packed biases
__device__ __forceinline__ void stage1_body(
        float2* swp, float2* sbp, float* sthr,
        int b, int tile, int ts,
        const float* __restrict__ x, const float* __restrict__ w1,
        const float* __restrict__ b1, const float* __restrict__ thr,
        float* __restrict__ out)
{
    for (int i = threadIdx.x; i < 16*12; i += 256) {
        int ocp = i / 12, j = i % 12;
        swp[i] = make_float2(w1[(2*ocp)*12 + j], w1[(2*ocp+1)*12 + j]);
    }
    if (threadIdx.x < 16)
        sbp[threadIdx.x] = make_float2(b1[2*threadIdx.x], b1[2*threadIdx.x+1]);
    if (threadIdx.x == 0) sthr[0] = thr[0];
    __syncthreads();

    int l1 = tile*256 + threadIdx.x;
    if (l1 >= L1) return;

    const float* xb = x + (((size_t)b*T_STEPS + ts)*4)*LEN0;
    float xr[4][5];
    u64   xr2[4][5];
    #pragma unroll
    for (int c = 0; c < 4; c++)
        #pragma unroll
        for (int j = 0; j < 5; j++) {
            int gi = 2*l1 - 1 + j;
            float v = (gi >= 0 && gi < LEN0) ? xb[c*LEN0 + gi] : 0.f;
            xr[c][j] = v;
            xr2[c][j] = PK(v, v);
        }

    const float th = sthr[0];
    unsigned mask = 0;
    const u64* swp64 = (const u64*)swp;

    #pragma unroll 2
    for (int ocp = 0; ocp < 16; ocp++) {
        u64 bb2 = *(const u64*)&sbp[ocp];
        u64 y0 = bb2, y1 = bb2, y2 = bb2;
        u64 wv[12];
        #pragma unroll
        for (int j = 0; j < 12; j++) wv[j] = swp64[ocp*12 + j];

        // cheap packed pass: per c apply k=2, then k=1, then k=0 (scalar nest order)
        #pragma unroll
        for (int c = 0; c < 4; c++) {
            u64 w0 = wv[c*3 + 0], w1v = wv[c*3 + 1], w2v = wv[c*3 + 2];
            y0 = FMA2(w2v, xr2[c][2], y0);
            y1 = FMA2(w2v, xr2[c][3], y1);
            y2 = FMA2(w2v, xr2[c][4], y2);
            y0 = FMA2(w1v, xr2[c][1], y0);
            y1 = FMA2(w1v, xr2[c][2], y1);
            y2 = FMA2(w1v, xr2[c][3], y2);
            y0 = FMA2(w0, xr2[c][0], y0);
            y1 = FMA2(w0, xr2[c][1], y1);
            y2 = FMA2(w0, xr2[c][2], y2);
        }

        float a0, b0, a1v, b1v, a2, b2v;
        UPK(y0, a0, b0);
        UPK(y1, a1v, b1v);
        UPK(y2, a2, b2v);

        // per-lane argmax (identical tie-break: strict >)
        int d0 = 0; float m0 = a0;
        if (a1v > m0) { m0 = a1v; d0 = 1; }
        if (a2  > m0) { m0 = a2;  d0 = 2; }
        int d1 = 0; float m1 = b0;
        if (b1v > m1) { m1 = b1v; d1 = 1; }
        if (b2v > m1) { m1 = b2v; d1 = 2; }

        // packed compensated recompute of the winning windows
        u64 s = bb2, cc = 0ULL;
        #pragma unroll
        for (int c = 0; c < 4; c++) {
            #pragma unroll
            for (int k = 0; k < 3; k++)
                kfma2(s, cc, wv[c*3 + k], PK(xr[c][d0 + k], xr[c][d1 + k]));
        }
        u64 cur2 = ADD2(s, cc);
        float cur0, cur1;
        UPK(cur2, cur0, cur1);

        // scalar LIF per lane
        float curv[2] = {cur0, cur1};
        #pragma unroll
        for (int h = 0; h < 2; h++) {
            int oc = 2*ocp + h;
            int   sidx = (b*C1 + oc)*L1 + l1;
            float mem  = g_mem0[sidx];
            float rst  = (mem - th > 0.f) ? 1.f : 0.f;
            float memn = fmaf(0.5f, mem, curv[h]) - rst*th;
            g_mem0[sidx] = memn;
            float spk = (memn - th > 0.f) ? 1.f : 0.f;
            if (spk > 0.f) mask |= (1u << oc);
            size_t oi = ((size_t)ts*NB + b)*32736 + (size_t)oc*L1 + l1;
            out[O_SPK0 + oi] = spk;
            out[O_MEM0 + oi] = memn;
        }
    }
    g_mask[ts & 1][b*L1 + l1] = mask;
}

// ================= fc body (fc1 + LIF2 + fc2 + LIF3) for step ts ============
__device__ __forceinline__ void fc_block(
        char* sm, int b, int ts,
        const float* __restrict__ fc1w, const float* __restrict__ fc1b,
        const float* __restrict__ fc2w, const float* __restrict__ fc2b,
        const float* __restrict__ thr, float* __restrict__ out)
{
    float* sfeat = (float*)sm;          // 128
    float* sfc1o = sfeat + 128;         // 256
    float* sspk2 = sfc1o + 256;         // 256
    int tid = threadIdx.x;

    if (tid < 128) sfeat[tid] = g_feat[(size_t)(ts&1)*NB*128 + b*128 + tid];
    __syncthreads();

    {
        int w = tid >> 5, lane = tid & 31;
        for (int oo = 0; oo < 32; oo++) {
            int o = w*32 + oo;
            float s = 0.f, c = 0.f;
            #pragma unroll
            for (int j = 0; j < 4; j++) {
                int f = lane + 32*j;
                kfma(s, c, fc1w[o*128 + f], sfeat[f]);
            }
            #pragma unroll
            for (int sh = 16; sh; sh >>= 1) {
                float s2 = __shfl_down_sync(0xffffffffu, s, sh);
                float c2 = __shfl_down_sync(0xffffffffu, c, sh);
                float ttv, ee;
                twoSum(s, s2, ttv, ee);
                c = (c + c2) + ee;
                s = ttv;
            }
            if (lane == 0) sfc1o[o] = s + c;
        }
    }
    __syncthreads();

    {
        float th = thr[2];
        int o = tid;
        float cur = sfc1o[o] + fc1b[o];
        float mem  = g_mem2[b*256 + o];
        float rst  = (mem - th > 0.f) ? 1.f : 0.f;
        float memn = fmaf(0.5f, mem, cur) - rst*th;
        g_mem2[b*256 + o] = memn;
        float spk = (memn - th > 0.f) ? 1.f : 0.f;
        sspk2[o] = spk;
        size_t oi = ((size_t)ts*NB + b)*256 + o;
        out[O_SPK2 + oi] = spk;
        out[O_MEM2 + oi] = memn;
    }
    __syncthreads();

    if (tid < 32) {
        float a0 = 0.f, e0 = 0.f, a1 = 0.f, e1 = 0.f;
        #pragma unroll
        for (int j = 0; j < 8; j++) {
            int o = tid + 32*j;
            float s = sspk2[o];
            kadd(a0, e0, fc2w[o] * s);
            kadd(a1, e1, fc2w[256 + o] * s);
        }
        #pragma unroll
        for (int sh = 16; sh; sh >>= 1) {
            float s2 = __shfl_down_sync(0xffffffffu, a0, sh);
            float c2 = __shfl_down_sync(0xffffffffu, e0, sh);
            float ttv, ee;
            twoSum(a0, s2, ttv, ee);
            e0 = (e0 + c2) + ee; a0 = ttv;
            s2 = __shfl_down_sync(0xffffffffu, a1, sh);
            c2 = __shfl_down_sync(0xffffffffu, e1, sh);
            twoSum(a1, s2, ttv, ee);
            e1 = (e1 + c2) + ee; a1 = ttv;
        }
        if (tid == 0) {
            float th = thr[3];
            float cc[2] = {(a0 + e0) + fc2b[0], (a1 + e1) + fc2b[1]};
            #pragma unroll
            for (int r = 0; r < 2; r++) {
                float mem  = g_mem3[b*2 + r];
                float rst  = (mem - th > 0.f) ? 1.f : 0.f;
                float memn = fmaf(0.5f, mem, cc[r]) - rst*th;
                g_mem3[b*2 + r] = memn;
                float spk = (memn - th > 0.f) ? 1.f : 0.f;
                size_t oi = ((size_t)ts*NB + b)*2 + r;
                out[O_SPK3 + oi] = spk;
                out[O_MEM3 + oi] = memn;
            }
        }
    }
}

// ================= stage2 for one batch (LUT already resident in smem) ======
__device__ __forceinline__ void stage2_batch(
        const float4* sT, unsigned* smask, float4* sc, float* saux,
        int g, int b, int t,
        const float* __restrict__ b2, const float* __restrict__ thr,
        float* __restrict__ out)
{
    int tid = threadIdx.x;
    const unsigned* gm = g_mask[t & 1] + b*L1;

    for (int i = tid; i < 1032; i += 256)
        smask[i] = (i >= 1 && i <= L1) ? gm[i-1] : 0u;
    if (tid < 8) saux[tid] = 0.f;
    if (tid >= 8 && tid < 12) saux[tid] = b2[g*4 + (tid-8)];
    if (tid == 12) saux[12] = thr[1];
    __syncthreads();

    // pass A: conv outputs into sc (zero-byte lookups skipped; exact +0)
    {
        int q0 = tid*4;
        unsigned mm[6];
        #pragma unroll
        for (int j = 0; j < 6; j++) mm[j] = smask[q0 + j];
        #pragma unroll
        for (int i = 0; i < 4; i++) {
            int q = q0 + i;
            if (q < L1) {
                float4 acc = make_float4(0.f, 0.f, 0.f, 0.f);
                #pragma unroll
                for (int k = 0; k < 3; k++) {
                    unsigned m = mm[i + k];
                    unsigned v0 = m & 255u, v1 = (m >> 8) & 255u;
                    unsigned v2 = (m >> 16) & 255u, v3 = m >> 24;
                    const float4* tk = sT + k*4*256;
                    float4 l0 = make_float4(0.f,0.f,0.f,0.f);
                    float4 l1 = l0, l2v = l0, l3 = l0;
                    if (v0) l0  = tk[v0];
                    if (v1) l1  = tk[256 + v1];
                    if (v2) l2v = tk[512 + v2];
                    if (v3) l3  = tk[768 + v3];
                    acc.x += (l0.x + l1.x) + (l2v.x + l3.x);
                    acc.y += (l0.y + l1.y) + (l2v.y + l3.y);
                    acc.z += (l0.z + l1.z) + (l2v.z + l3.z);
                    acc.w += (l0.w + l1.w) + (l2v.w + l3.w);
                }
                sc[q] = acc;
            }
        }
    }
    __syncthreads();

    // pass B: maxpool + LIF1 + writes + spike counts
    const float th = saux[12];
    const float bs0 = saux[8], bs1 = saux[9], bs2 = saux[10], bs3 = saux[11];
    float cnt0[4] = {0.f,0.f,0.f,0.f}, cnt1[4] = {0.f,0.f,0.f,0.f};

    for (int l = tid; l < L2; l += 256) {
        float4 c0 = sc[2*l], c1 = sc[2*l + 1], c2 = sc[2*l + 2];
        float cur[4];
        cur[0] = fmaxf(c0.x + bs0, fmaxf(c1.x + bs0, c2.x + bs0));
        cur[1] = fmaxf(c0.y + bs1, fmaxf(c1.y + bs1, c2.y + bs1));
        cur[2] = fmaxf(c0.z + bs2, fmaxf(c1.z + bs2, c2.z + bs2));
        cur[3] = fmaxf(c0.w + bs3, fmaxf(c1.w + bs3, c2.w + bs3));
        #pragma unroll
        for (int o = 0; o < 4; o++) {
            int oc = g*4 + o;
            int sidx = (b*C2 + oc)*L2 + l;
            float mem  = g_mem1[sidx];
            float rst  = (mem - th > 0.f) ? 1.f : 0.f;
            float memn = fmaf(0.5f, mem, cur[o]) - rst*th;
            g_mem1[sidx] = memn;
            float spk = (memn - th > 0.f) ? 1.f : 0.f;
            size_t oi = ((size_t)t*NB + b)*32704 + (size_t)oc*L2 + l;
            out[O_SPK1 + oi] = spk;
            out[O_MEM1 + oi] = memn;
            if (l < 256)  cnt0[o] += spk;
            if (l >= 255) cnt1[o] += spk;
        }
    }

    {
        int lane = tid & 31;
        #pragma unroll
        for (int o = 0; o < 4; o++) {
            float a = cnt0[o], c = cnt1[o];
            #pragma unroll
            for (int sh = 16; sh; sh >>= 1) {
                a += __shfl_down_sync(0xffffffffu, a, sh);
                c += __shfl_down_sync(0xffffffffu, c, sh);
            }
            if (lane == 0) {
                atomicAdd(&saux[o*2 + 0], a);
                atomicAdd(&saux[o*2 + 1], c);
            }
        }
    }
    __syncthreads();
    if (tid < 8)
        g_feat[(size_t)(t&1)*NB*128 + b*128 + g*8 + tid] = saux[tid] * 0.00390625f;
}

// ================= stage2 block: LUT loaded once, two batches processed =====
__device__ __forceinline__ void stage2_body2(
        char* sm, int g, int bpair, int t,
        const float* __restrict__ b2, const float* __restrict__ thr,
        float* __restrict__ out)
{
    float4*   sT    = (float4*)(sm + SM_T);
    unsigned* smask = (unsigned*)(sm + SM_MASK);
    float4*   sc    = (float4*)(sm + SM_SC);
    float*    saux  = (float*)(sm + SM_AUX);

    int tid = threadIdx.x;
    const float4* lutg = (const float4*)g_lut + (size_t)g*12*256;
    for (int i = tid; i < 12*256; i += 256) sT[i] = lutg[i];

    stage2_batch(sT, smask, sc, saux, g, 2*bpair + 0, t, b2, thr, out);
    __syncthreads();
    stage2_batch(sT, smask, sc, saux, g, 2*bpair + 1, t, b2, thr, out);
}

// ================= prologue: stage1 for t = 0 =================
__global__ void __launch_bounds__(256) k_pro(
        const float* __restrict__ x, const float* __restrict__ w1,
        const float* __restrict__ b1, const float* __restrict__ thr,
        float* __restrict__ out)
{
    __shared__ float2 swp[16*12];
    __shared__ float2 sbp[16];
    __shared__ float  sthr[1];
    stage1_body(swp, sbp, sthr, blockIdx.y, blockIdx.x, 0, x, w1, b1, thr, out);
}

// ================= fused: stage2(t) + stage1(t+1) + fc(t-1) =================
// blocks [0,512): stage2 (16 g x 32 batch-pairs); [512,768): stage1(t+1);
// [768,832): fc(t-1)
__global__ void __launch_bounds__(256, 3) k_fused(
        const float* __restrict__ x,
        const float* __restrict__ w1, const float* __restrict__ b1,
        const float* __restrict__ b2,
        const float* __restrict__ fc1w, const float* __restrict__ fc1b,
        const float* __restrict__ fc2w, const float* __restrict__ fc2b,
        const float* __restrict__ thr, float* __restrict__ out, int t)
{
    extern __shared__ char sm[];
    int bid = blockIdx.x;
    if (bid < 512) {
        stage2_body2(sm, bid & 15, bid >> 4, t, b2, thr, out);
    } else if (bid < 768) {
        if (t + 1 < T_STEPS) {
            int r = bid - 512;
            float2* swp = (float2*)sm;
            float2* sbp = swp + 16*12;
            float*  sthr = (float*)(sbp + 16);
            stage1_body(swp, sbp, sthr, r >> 2, r & 3, t + 1, x, w1, b1, thr, out);
        }
    } else {
        if (t >= 1)
            fc_block(sm, bid - 768, t - 1, fc1w, fc1b, fc2w, fc2b, thr, out);
    }
}

// ================= tail: fc for t = 31 =================
__global__ void __launch_bounds__(256) k_tail(
        const float* __restrict__ fc1w, const float* __restrict__ fc1b,
        const float* __restrict__ fc2w, const float* __restrict__ fc2b,
        const float* __restrict__ thr, float* __restrict__ out)
{
    __shared__ char sm[(128 + 256 + 256) * 4];
    fc_block(sm, blockIdx.x, T_STEPS - 1, fc1w, fc1b, fc2w, fc2b, thr, out);
}

extern "C" void kernel_launch(void* const* d_in, const int* in_sizes, int n_in,
                              void* d_out, int out_size)
{
    const float* x   = (const float*)d_in[0];
    const float* c1w = (const float*)d_in[1];
    const float* c1b = (const float*)d_in[2];
    const float* c2w = (const float*)d_in[3];
    const float* c2b = (const float*)d_in[4];
    const float* f1w = (const float*)d_in[5];
    const float* f1b = (const float*)d_in[6];
    const float* f2w = (const float*)d_in[7];
    const float* f2b = (const float*)d_in[8];
    const float* thr = (const float*)d_in[9];
    float* out = (float*)d_out;

    cudaFuncSetAttribute(k_fused, cudaFuncAttributeMaxDynamicSharedMemorySize, SMEM2);

    k_init<<<256, 256>>>();
    k_lut<<<768, 256>>>(c2w);
    k_pro<<<dim3(4, NB), 256>>>(x, c1w, c1b, thr, out);
    for (int t = 0; t < T_STEPS; t++) {
        k_fused<<<832, 256, SMEM2>>>(x, c1w, c1b, c2b, f1w, f1b, f2w, f2b,
                                     thr, out, t);
    }
    k_tail<<<NB, 256>>>(f1w, f1b, f2w, f2b, thr, out);
}

// round 9
// speedup vs baseline: 1.2489x; 1.0039x over previous
#include <cuda_runtime.h>
#include <cstddef>

#define T_STEPS 32
#define NB      64
#define LEN0    2048
#define L1      1023
#define L2      511
#define C1      32
#define C2      64

// ---- output layout offsets ----
static const size_t O_SPK0 = 0;
static const size_t O_SPK1 = (size_t)T_STEPS*NB*32736;
static const size_t O_SPK2 = O_SPK1 + (size_t)T_STEPS*NB*32704;
static const size_t O_SPK3 = O_SPK2 + (size_t)T_STEPS*NB*256;
static const size_t O_MEM0 = O_SPK3 + (size_t)T_STEPS*NB*2;
static const size_t O_MEM1 = O_MEM0 + (size_t)T_STEPS*NB*32736;
static const size_t O_MEM2 = O_MEM1 + (size_t)T_STEPS*NB*32704;
static const size_t O_MEM3 = O_MEM2 + (size_t)T_STEPS*NB*256;

// ---- persistent state / scratch ----
__device__ float    g_mem0[NB*C1*L1];
__device__ float    g_mem1[NB*C2*L2];
__device__ float    g_mem2[NB*256];
__device__ float    g_mem3[NB*2];
__device__ unsigned g_mask[2][NB*L1];
__device__ float    g_feat[2*NB*128];
// LUT: [grp(16)][kb(12)][v(256)] float4 (4 oc per group)
__device__ __align__(16) float g_lut[16*12*256*4];

// smem layout for fused kernel (stage2 role)
#define SM_T    0
#define SM_MASK 49152
#define SM_SC   (49152 + 4128)
#define SM_AUX  (SM_SC + 16368)
#define SMEM2   (SM_AUX + 64)     // 69,712 bytes -> 3 CTAs/SM

typedef unsigned long long u64;

// ================= packed f32x2 helpers (bit-identical per-lane rounding) ====
__device__ __forceinline__ u64 PK(float lo, float hi) {
    u64 r; asm("mov.b64 %0,{%1,%2};" : "=l"(r) : "f"(lo), "f"(hi)); return r;
}
__device__ __forceinline__ void UPK(u64 v, float& lo, float& hi) {
    asm("mov.b64 {%0,%1},%2;" : "=f"(lo), "=f"(hi) : "l"(v));
}
__device__ __forceinline__ u64 FMA2(u64 a, u64 b, u64 c) {
    u64 d; asm("fma.rn.f32x2 %0,%1,%2,%3;" : "=l"(d) : "l"(a), "l"(b), "l"(c)); return d;
}
__device__ __forceinline__ u64 ADD2(u64 a, u64 b) {
    u64 d; asm("add.rn.f32x2 %0,%1,%2;" : "=l"(d) : "l"(a), "l"(b)); return d;
}
__device__ __forceinline__ u64 MUL2(u64 a, u64 b) {
    u64 d; asm("mul.rn.f32x2 %0,%1,%2;" : "=l"(d) : "l"(a), "l"(b)); return d;
}
__device__ __forceinline__ u64 NEG2(u64 a) { return a ^ 0x8000000080000000ULL; }

__device__ __forceinline__ void twoSum2(u64 a, u64 b, u64& s, u64& e) {
    s = ADD2(a, b);
    u64 bp = ADD2(s, NEG2(a));
    u64 ap = ADD2(s, NEG2(bp));
    e = ADD2(ADD2(b, NEG2(bp)), ADD2(a, NEG2(ap)));
}
__device__ __forceinline__ void kfma2(u64& s, u64& c, u64 a, u64 b) {
    u64 p = MUL2(a, b);
    u64 e = FMA2(a, b, NEG2(p));
    u64 t, e2;
    twoSum2(s, p, t, e2);
    c = ADD2(c, e2);
    s = t;
    c = ADD2(c, e);
}

// ================= scalar compensated helpers (fc path) =================
__device__ __forceinline__ void twoSum(float a, float b, float& s, float& e) {
    s = a + b;
    float bp = s - a;
    float ap = s - bp;
    e = (b - bp) + (a - ap);
}
__device__ __forceinline__ void kadd(float& s, float& c, float v) {
    float t, e;
    twoSum(s, v, t, e);
    c += e;
    s = t;
}
__device__ __forceinline__ void kfma(float& s, float& c, float a, float b) {
    float p = a * b;
    float e = fmaf(a, b, -p);
    kadd(s, c, p);
    c += e;
}

// ================= init: zero membrane states =================
__global__ void k_init() {
    const int n0 = NB*C1*L1, n1 = NB*C2*L2, n2 = NB*256, n3 = NB*2;
    const int n = n0 + n1 + n2 + n3;
    for (int i = blockIdx.x*blockDim.x + threadIdx.x; i < n; i += gridDim.x*blockDim.x) {
        if (i < n0) g_mem0[i] = 0.f;
        else if (i < n0+n1) g_mem1[i-n0] = 0.f;
        else if (i < n0+n1+n2) g_mem2[i-n0-n1] = 0.f;
        else g_mem3[i-n0-n1-n2] = 0.f;
    }
}

// ================= LUT build (double, rounded once) =================
__global__ void k_lut(const float* __restrict__ w2) {
    int i = blockIdx.x*blockDim.x + threadIdx.x;
    if (i >= 16*12*256*4) return;
    int ocl = i & 3;
    int v   = (i >> 2) & 255;
    int tt  = i >> 10;
    int kb  = tt % 12;
    int g   = tt / 12;
    int k   = kb >> 2;
    int b4  = kb & 3;
    int oc  = g*4 + ocl;
    double s = 0.0;
    #pragma unroll
    for (int bit = 0; bit < 8; bit++)
        if ((v >> bit) & 1)
            s += (double)w2[(oc*32 + b4*8 + bit)*3 + k];
    g_lut[i] = (float)s;
}

// ================= stage1 body: conv1 + maxpool + LIF0 (f32x2 packed) =======
__device__ __forceinline__ void stage1_body(
        float2* swp, float2* sbp, float* sthr,
        int b, int tile, int ts,
        const float* __restrict__ x, const float* __restrict__ w1,
        const float* __restrict__ b1, const float* __restrict__ thr,
        float* __restrict__ out)
{
    for (int i = threadIdx.x; i < 16*12; i += 256) {
        int ocp = i / 12, j = i % 12;
        swp[i] = make_float2(w1[(2*ocp)*12 + j], w1[(2*ocp+1)*12 + j]);
    }
    if (threadIdx.x < 16)
        sbp[threadIdx.x] = make_float2(b1[2*threadIdx.x], b1[2*threadIdx.x+1]);
    if (threadIdx.x == 0) sthr[0] = thr[0];
    __syncthreads();

    int l1 = tile*256 + threadIdx.x;
    if (l1 >= L1) return;

    const float* xb = x + (((size_t)b*T_STEPS + ts)*4)*LEN0;
    float xr[4][5];
    u64   xr2[4][5];
    #pragma unroll
    for (int c = 0; c < 4; c++)
        #pragma unroll
        for (int j = 0; j < 5; j++) {
            int gi = 2*l1 - 1 + j;
            float v = (gi >= 0 && gi < LEN0) ? xb[c*LEN0 + gi] : 0.f;
            xr[c][j] = v;
            xr2[c][j] = PK(v, v);
        }

    const float th = sthr[0];
    unsigned mask = 0;
    const u64* swp64 = (const u64*)swp;

    #pragma unroll 4
    for (int ocp = 0; ocp < 16; ocp++) {
        u64 bb2 = *(const u64*)&sbp[ocp];
        u64 y0 = bb2, y1 = bb2, y2 = bb2;
        u64 wv[12];
        #pragma unroll
        for (int j = 0; j < 12; j++) wv[j] = swp64[ocp*12 + j];

        // prefetch membrane states early (hides L2 latency under math below)
        int sidx0 = (b*C1 + 2*ocp + 0)*L1 + l1;
        int sidx1 = (b*C1 + 2*ocp + 1)*L1 + l1;
        float mem_pref0 = g_mem0[sidx0];
        float mem_pref1 = g_mem0[sidx1];

        #pragma unroll
        for (int c = 0; c < 4; c++) {
            u64 w0 = wv[c*3 + 0], w1v = wv[c*3 + 1], w2v = wv[c*3 + 2];
            y0 = FMA2(w2v, xr2[c][2], y0);
            y1 = FMA2(w2v, xr2[c][3], y1);
            y2 = FMA2(w2v, xr2[c][4], y2);
            y0 = FMA2(w1v, xr2[c][1], y0);
            y1 = FMA2(w1v, xr2[c][2], y1);
            y2 = FMA2(w1v, xr2[c][3], y2);
            y0 = FMA2(w0, xr2[c][0], y0);
            y1 = FMA2(w0, xr2[c][1], y1);
            y2 = FMA2(w0, xr2[c][2], y2);
        }

        float a0, b0, a1v, b1v, a2, b2v;
        UPK(y0, a0, b0);
        UPK(y1, a1v, b1v);
        UPK(y2, a2, b2v);

        int d0 = 0; float m0 = a0;
        if (a1v > m0) { m0 = a1v; d0 = 1; }
        if (a2  > m0) { m0 = a2;  d0 = 2; }
        int d1 = 0; float m1 = b0;
        if (b1v > m1) { m1 = b1v; d1 = 1; }
        if (b2v > m1) { m1 = b2v; d1 = 2; }

        u64 s = bb2, cc = 0ULL;
        #pragma unroll
        for (int c = 0; c < 4; c++) {
            #pragma unroll
            for (int k = 0; k < 3; k++)
                kfma2(s, cc, wv[c*3 + k], PK(xr[c][d0 + k], xr[c][d1 + k]));
        }
        u64 cur2 = ADD2(s, cc);
        float cur0, cur1;
        UPK(cur2, cur0, cur1);

        float curv[2] = {cur0, cur1};
        float memv[2] = {mem_pref0, mem_pref1};
        int   sidxv[2] = {sidx0, sidx1};
        #pragma unroll
        for (int h = 0; h < 2; h++) {
            int oc = 2*ocp + h;
            float mem  = memv[h];
            float rst  = (mem - th > 0.f) ? 1.f : 0.f;
            float memn = fmaf(0.5f, mem, curv[h]) - rst*th;
            g_mem0[sidxv[h]] = memn;
            float spk = (memn - th > 0.f) ? 1.f : 0.f;
            if (spk > 0.f) mask |= (1u << oc);
            size_t oi = ((size_t)ts*NB + b)*32736 + (size_t)oc*L1 + l1;
            out[O_SPK0 + oi] = spk;
            out[O_MEM0 + oi] = memn;
        }
    }
    g_mask[ts & 1][b*L1 + l1] = mask;
}

// ================= fc body (fc1 + LIF2 + fc2 + LIF3) for step ts ============
__device__ __forceinline__ void fc_block(
        char* sm, int b, int ts,
        const float* __restrict__ fc1w, const float* __restrict__ fc1b,
        const float* __restrict__ fc2w, const float* __restrict__ fc2b,
        const float* __restrict__ thr, float* __restrict__ out)
{
    float* sfeat = (float*)sm;          // 128
    float* sfc1o = sfeat + 128;         // 256
    float* sspk2 = sfc1o + 256;         // 256
    int tid = threadIdx.x;

    if (tid < 128) sfeat[tid] = g_feat[(size_t)(ts&1)*NB*128 + b*128 + tid];
    __syncthreads();

    {
        int w = tid >> 5, lane = tid & 31;
        for (int oo = 0; oo < 32; oo++) {
            int o = w*32 + oo;
            float s = 0.f, c = 0.f;
            #pragma unroll
            for (int j = 0; j < 4; j++) {
                int f = lane + 32*j;
                kfma(s, c, fc1w[o*128 + f], sfeat[f]);
            }
            #pragma unroll
            for (int sh = 16; sh; sh >>= 1) {
                float s2 = __shfl_down_sync(0xffffffffu, s, sh);
                float c2 = __shfl_down_sync(0xffffffffu, c, sh);
                float ttv, ee;
                twoSum(s, s2, ttv, ee);
                c = (c + c2) + ee;
                s = ttv;
            }
            if (lane == 0) sfc1o[o] = s + c;
        }
    }
    __syncthreads();

    {
        float th = thr[2];
        int o = tid;
        float cur = sfc1o[o] + fc1b[o];
        float mem  = g_mem2[b*256 + o];
        float rst  = (mem - th > 0.f) ? 1.f : 0.f;
        float memn = fmaf(0.5f, mem, cur) - rst*th;
        g_mem2[b*256 + o] = memn;
        float spk = (memn - th > 0.f) ? 1.f : 0.f;
        sspk2[o] = spk;
        size_t oi = ((size_t)ts*NB + b)*256 + o;
        out[O_SPK2 + oi] = spk;
        out[O_MEM2 + oi] = memn;
    }
    __syncthreads();

    if (tid < 32) {
        float a0 = 0.f, e0 = 0.f, a1 = 0.f, e1 = 0.f;
        #pragma unroll
        for (int j = 0; j < 8; j++) {
            int o = tid + 32*j;
            float s = sspk2[o];
            kadd(a0, e0, fc2w[o] * s);
            kadd(a1, e1, fc2w[256 + o] * s);
        }
        #pragma unroll
        for (int sh = 16; sh; sh >>= 1) {
            float s2 = __shfl_down_sync(0xffffffffu, a0, sh);
            float c2 = __shfl_down_sync(0xffffffffu, e0, sh);
            float ttv, ee;
            twoSum(a0, s2, ttv, ee);
            e0 = (e0 + c2) + ee; a0 = ttv;
            s2 = __shfl_down_sync(0xffffffffu, a1, sh);
            c2 = __shfl_down_sync(0xffffffffu, e1, sh);
            twoSum(a1, s2, ttv, ee);
            e1 = (e1 + c2) + ee; a1 = ttv;
        }
        if (tid == 0) {
            float th = thr[3];
            float cc[2] = {(a0 + e0) + fc2b[0], (a1 + e1) + fc2b[1]};
            #pragma unroll
            for (int r = 0; r < 2; r++) {
                float mem  = g_mem3[b*2 + r];
                float rst  = (mem - th > 0.f) ? 1.f : 0.f;
                float memn = fmaf(0.5f, mem, cc[r]) - rst*th;
                g_mem3[b*2 + r] = memn;
                float spk = (memn - th > 0.f) ? 1.f : 0.f;
                size_t oi = ((size_t)ts*NB + b)*2 + r;
                out[O_SPK3 + oi] = spk;
                out[O_MEM3 + oi] = memn;
            }
        }
    }
}

// ================= stage2 for one batch (LUT already resident in smem) ======
__device__ __forceinline__ void stage2_batch(
        const float4* sT, unsigned* smask, float4* sc, float* saux,
        int g, int b, int t,
        const float* __restrict__ b2, const float* __restrict__ thr,
        float* __restrict__ out)
{
    int tid = threadIdx.x;
    const unsigned* gm = g_mask[t & 1] + b*L1;

    for (int i = tid; i < 1032; i += 256)
        smask[i] = (i >= 1 && i <= L1) ? gm[i-1] : 0u;
    if (tid < 8) saux[tid] = 0.f;
    if (tid >= 8 && tid < 12) saux[tid] = b2[g*4 + (tid-8)];
    if (tid == 12) saux[12] = thr[1];

    // ---- prefetch membrane states for pass B (latency hidden by pass A) ----
    float pm[2][4];
    #pragma unroll
    for (int it = 0; it < 2; it++) {
        int l = tid + it*256;
        if (l < L2) {
            #pragma unroll
            for (int o = 0; o < 4; o++)
                pm[it][o] = g_mem1[(b*C2 + g*4 + o)*L2 + l];
        }
    }
    __syncthreads();

    // pass A: conv outputs into sc (zero-byte lookups skipped; exact +0)
    {
        int q0 = tid*4;
        unsigned mm[6];
        #pragma unroll
        for (int j = 0; j < 6; j++) mm[j] = smask[q0 + j];
        #pragma unroll
        for (int i = 0; i < 4; i++) {
            int q = q0 + i;
            if (q < L1) {
                float4 acc = make_float4(0.f, 0.f, 0.f, 0.f);
                #pragma unroll
                for (int k = 0; k < 3; k++) {
                    unsigned m = mm[i + k];
                    unsigned v0 = m & 255u, v1 = (m >> 8) & 255u;
                    unsigned v2 = (m >> 16) & 255u, v3 = m >> 24;
                    const float4* tk = sT + k*4*256;
                    float4 l0 = make_float4(0.f,0.f,0.f,0.f);
                    float4 l1 = l0, l2v = l0, l3 = l0;
                    if (v0) l0  = tk[v0];
                    if (v1) l1  = tk[256 + v1];
                    if (v2) l2v = tk[512 + v2];
                    if (v3) l3  = tk[768 + v3];
                    acc.x += (l0.x + l1.x) + (l2v.x + l3.x);
                    acc.y += (l0.y + l1.y) + (l2v.y + l3.y);
                    acc.z += (l0.z + l1.z) + (l2v.z + l3.z);
                    acc.w += (l0.w + l1.w) + (l2v.w + l3.w);
                }
                sc[q] = acc;
            }
        }
    }
    __syncthreads();

    // pass B: maxpool + LIF1 + writes + spike counts (mem pre-loaded)
    const float th = saux[12];
    const float bs0 = saux[8], bs1 = saux[9], bs2 = saux[10], bs3 = saux[11];
    float cnt0[4] = {0.f,0.f,0.f,0.f}, cnt1[4] = {0.f,0.f,0.f,0.f};

    #pragma unroll
    for (int it = 0; it < 2; it++) {
        int l = tid + it*256;
        if (l < L2) {
            float4 c0 = sc[2*l], c1 = sc[2*l + 1], c2 = sc[2*l + 2];
            float cur[4];
            cur[0] = fmaxf(c0.x + bs0, fmaxf(c1.x + bs0, c2.x + bs0));
            cur[1] = fmaxf(c0.y + bs1, fmaxf(c1.y + bs1, c2.y + bs1));
            cur[2] = fmaxf(c0.z + bs2, fmaxf(c1.z + bs2, c2.z + bs2));
            cur[3] = fmaxf(c0.w + bs3, fmaxf(c1.w + bs3, c2.w + bs3));
            #pragma unroll
            for (int o = 0; o < 4; o++) {
                int oc = g*4 + o;
                float mem  = pm[it][o];
                float rst  = (mem - th > 0.f) ? 1.f : 0.f;
                float memn = fmaf(0.5f, mem, cur[o]) - rst*th;
                g_mem1[(b*C2 + oc)*L2 + l] = memn;
                float spk = (memn - th > 0.f) ? 1.f : 0.f;
                size_t oi = ((size_t)t*NB + b)*32704 + (size_t)oc*L2 + l;
                out[O_SPK1 + oi] = spk;
                out[O_MEM1 + oi] = memn;
                if (l < 256)  cnt0[o] += spk;
                if (l >= 255) cnt1[o] += spk;
            }
        }
    }

    {
        int lane = tid & 31;
        #pragma unroll
        for (int o = 0; o < 4; o++) {
            float a = cnt0[o], c = cnt1[o];
            #pragma unroll
            for (int sh = 16; sh; sh >>= 1) {
                a += __shfl_down_sync(0xffffffffu, a, sh);
                c += __shfl_down_sync(0xffffffffu, c, sh);
            }
            if (lane == 0) {
                atomicAdd(&saux[o*2 + 0], a);
                atomicAdd(&saux[o*2 + 1], c);
            }
        }
    }
    __syncthreads();
    if (tid < 8)
        g_feat[(size_t)(t&1)*NB*128 + b*128 + g*8 + tid] = saux[tid] * 0.00390625f;
}

// ================= stage2 block: LUT loaded once, two batches processed =====
__device__ __forceinline__ void stage2_body2(
        char* sm, int g, int bpair, int t,
        const float* __restrict__ b2, const float* __restrict__ thr,
        float* __restrict__ out)
{
    float4*   sT    = (float4*)(sm + SM_T);
    unsigned* smask = (unsigned*)(sm + SM_MASK);
    float4*   sc    = (float4*)(sm + SM_SC);
    float*    saux  = (float*)(sm + SM_AUX);

    int tid = threadIdx.x;
    const float4* lutg = (const float4*)g_lut + (size_t)g*12*256;
    for (int i = tid; i < 12*256; i += 256) sT[i] = lutg[i];

    stage2_batch(sT, smask, sc, saux, g, 2*bpair + 0, t, b2, thr, out);
    __syncthreads();
    stage2_batch(sT, smask, sc, saux, g, 2*bpair + 1, t, b2, thr, out);
}

// ================= prologue: stage1 for t = 0 =================
__global__ void __launch_bounds__(256) k_pro(
        const float* __restrict__ x, const float* __restrict__ w1,
        const float* __restrict__ b1, const float* __restrict__ thr,
        float* __restrict__ out)
{
    __shared__ float2 swp[16*12];
    __shared__ float2 sbp[16];
    __shared__ float  sthr[1];
    stage1_body(swp, sbp, sthr, blockIdx.y, blockIdx.x, 0, x, w1, b1, thr, out);
}

// ================= fused: stage2(t) + stage1(t+1) + fc(t-1) =================
__global__ void __launch_bounds__(256, 3) k_fused(
        const float* __restrict__ x,
        const float* __restrict__ w1, const float* __restrict__ b1,
        const float* __restrict__ b2,
        const float* __restrict__ fc1w, const float* __restrict__ fc1b,
        const float* __restrict__ fc2w, const float* __restrict__ fc2b,
        const float* __restrict__ thr, float* __restrict__ out, int t)
{
    extern __shared__ char sm[];
    int bid = blockIdx.x;
    if (bid < 512) {
        stage2_body2(sm, bid & 15, bid >> 4, t, b2, thr, out);
    } else if (bid < 768) {
        if (t + 1 < T_STEPS) {
            int r = bid - 512;
            float2* swp = (float2*)sm;
            float2* sbp = swp + 16*12;
            float*  sthr = (float*)(sbp + 16);
            stage1_body(swp, sbp, sthr, r >> 2, r & 3, t + 1, x, w1, b1, thr, out);
        }
    } else {
        if (t >= 1)
            fc_block(sm, bid - 768, t - 1, fc1w, fc1b, fc2w, fc2b, thr, out);
    }
}

// ================= tail: fc for t = 31 =================
__global__ void __launch_bounds__(256) k_tail(
        const float* __restrict__ fc1w, const float* __restrict__ fc1b,
        const float* __restrict__ fc2w, const float* __restrict__ fc2b,
        const float* __restrict__ thr, float* __restrict__ out)
{
    __shared__ char sm[(128 + 256 + 256) * 4];
    fc_block(sm, blockIdx.x, T_STEPS - 1, fc1w, fc1b, fc2w, fc2b, thr, out);
}

extern "C" void kernel_launch(void* const* d_in, const int* in_sizes, int n_in,
                              void* d_out, int out_size)
{
    const float* x   = (const float*)d_in[0];
    const float* c1w = (const float*)d_in[1];
    const float* c1b = (const float*)d_in[2];
    const float* c2w = (const float*)d_in[3];
    const float* c2b = (const float*)d_in[4];
    const float* f1w = (const float*)d_in[5];
    const float* f1b = (const float*)d_in[6];
    const float* f2w = (const float*)d_in[7];
    const float* f2b = (const float*)d_in[8];
    const float* thr = (const float*)d_in[9];
    float* out = (float*)d_out;

    cudaFuncSetAttribute(k_fused, cudaFuncAttributeMaxDynamicSharedMemorySize, SMEM2);

    k_init<<<256, 256>>>();
    k_lut<<<768, 256>>>(c2w);
    k_pro<<<dim3(4, NB), 256>>>(x, c1w, c1b, thr, out);
    for (int t = 0; t < T_STEPS; t++) {
        k_fused<<<832, 256, SMEM2>>>(x, c1w, c1b, c2b, f1w, f1b, f2w, f2b,
                                     thr, out, t);
    }
    k_tail<<<NB, 256>>>(f1w, f1b, f2w, f2b, thr, out);
}

// round 11
// speedup vs baseline: 1.2775x; 1.0229x over previous
#include <cuda_runtime.h>
#include <cstddef>
#include <math.h>

#define T_STEPS 32
#define NB      64
#define LEN0    2048
#define L1      1023
#define L2      511
#define C1      32
#define C2      64

// ---- output layout offsets ----
static const size_t O_SPK0 = 0;
static const size_t O_SPK1 = (size_t)T_STEPS*NB*32736;
static const size_t O_SPK2 = O_SPK1 + (size_t)T_STEPS*NB*32704;
static const size_t O_SPK3 = O_SPK2 + (size_t)T_STEPS*NB*256;
static const size_t O_MEM0 = O_SPK3 + (size_t)T_STEPS*NB*2;
static const size_t O_MEM1 = O_MEM0 + (size_t)T_STEPS*NB*32736;
static const size_t O_MEM2 = O_MEM1 + (size_t)T_STEPS*NB*32704;
static const size_t O_MEM3 = O_MEM2 + (size_t)T_STEPS*NB*256;

// ---- persistent state / scratch ----
__device__ float    g_mem0[NB*C1*L1];
__device__ float    g_mem1[NB*C2*L2];
__device__ float    g_mem2[NB*256];
__device__ float    g_mem3[NB*2];
__device__ unsigned g_mask[2][NB*L1];
__device__ float    g_feat[2*NB*128];
// LUT: [grp(16)][kb(12)][v(256)] float4 (4 oc per group)
__device__ __align__(16) float g_lut[16*12*256*4];

// k_fused dynamic smem: 48KB LUT shared + 2 per-half slices
// slice: masks 4128 + sc 16368 + aux 64 = 20560
#define SM_HALF   20560
#define SM_BASE   49152
#define SMEM2     (SM_BASE + 2*SM_HALF)   // 90,272 B -> 2 CTAs/SM @512thr

// ================= scalar compensated helpers =================
__device__ __forceinline__ void twoSum(float a, float b, float& s, float& e) {
    s = a + b;
    float bp = s - a;
    float ap = s - bp;
    e = (b - bp) + (a - ap);
}
__device__ __forceinline__ void kadd(float& s, float& c, float v) {
    float t, e;
    twoSum(s, v, t, e);
    c += e;
    s = t;
}
__device__ __forceinline__ void kfma(float& s, float& c, float a, float b) {
    float p = a * b;
    float e = fmaf(a, b, -p);
    kadd(s, c, p);
    c += e;
}

// ================= init: zero membrane states =================
__global__ void k_init() {
    const int n0 = NB*C1*L1, n1 = NB*C2*L2, n2 = NB*256, n3 = NB*2;
    const int n = n0 + n1 + n2 + n3;
    for (int i = blockIdx.x*blockDim.x + threadIdx.x; i < n; i += gridDim.x*blockDim.x) {
        if (i < n0) g_mem0[i] = 0.f;
        else if (i < n0+n1) g_mem1[i-n0] = 0.f;
        else if (i < n0+n1+n2) g_mem2[i-n0-n1] = 0.f;
        else g_mem3[i-n0-n1-n2] = 0.f;
    }
}

// ================= LUT build (double, rounded once) =================
__global__ void k_lut(const float* __restrict__ w2) {
    int i = blockIdx.x*blockDim.x + threadIdx.x;
    if (i >= 16*12*256*4) return;
    int ocl = i & 3;
    int v   = (i >> 2) & 255;
    int tt  = i >> 10;
    int kb  = tt % 12;
    int g   = tt / 12;
    int k   = kb >> 2;
    int b4  = kb & 3;
    int oc  = g*4 + ocl;
    double s = 0.0;
    #pragma unroll
    for (int bit = 0; bit < 8; bit++)
        if ((v >> bit) & 1)
            s += (double)w2[(oc*32 + b4*8 + bit)*3 + k];
    g_lut[i] = (float)s;
}

// ================= stage1 task: conv1 + maxpool + LIF0 (one tile, 256 lanes) =
// exact compensated recompute of the pool-winning window (round-7 numerics)
__device__ __forceinline__ void stage1_task(
        const float* sw, const float* sb, float th,
        int b, int tile, int ts, int ltid,
        const float* __restrict__ x, float* __restrict__ out)
{
    int l1 = tile*256 + ltid;
    if (l1 >= L1) return;

    const float* xb = x + (((size_t)b*T_STEPS + ts)*4)*LEN0;
    float xr[4][5];
    #pragma unroll
    for (int c = 0; c < 4; c++)
        #pragma unroll
        for (int j = 0; j < 5; j++) {
            int gi = 2*l1 - 1 + j;
            xr[c][j] = (gi >= 0 && gi < LEN0) ? xb[c*LEN0 + gi] : 0.f;
        }

    unsigned mask = 0;
    #pragma unroll 2
    for (int oc = 0; oc < C1; oc++) {
        float bb = sb[oc];
        // prefetch membrane state early (hides L2 latency under math below)
        int   sidx = (b*C1 + oc)*L1 + l1;
        float mem  = g_mem0[sidx];

        float y0 = bb, y1 = bb, y2 = bb;
        #pragma unroll
        for (int c = 0; c < 4; c++) {
            float w0 = sw[oc*12 + c*3 + 0];
            float w1v = sw[oc*12 + c*3 + 1];
            float w2v = sw[oc*12 + c*3 + 2];
            y0 = fmaf(w0, xr[c][0], fmaf(w1v, xr[c][1], fmaf(w2v, xr[c][2], y0)));
            y1 = fmaf(w0, xr[c][1], fmaf(w1v, xr[c][2], fmaf(w2v, xr[c][3], y1)));
            y2 = fmaf(w0, xr[c][2], fmaf(w1v, xr[c][3], fmaf(w2v, xr[c][4], y2)));
        }
        int dmax = 0;
        float ymax = y0;
        if (y1 > ymax) { ymax = y1; dmax = 1; }
        if (y2 > ymax) { ymax = y2; dmax = 2; }

        float s = bb, cc = 0.f;
        #pragma unroll
        for (int c = 0; c < 4; c++) {
            #pragma unroll
            for (int k = 0; k < 3; k++)
                kfma(s, cc, sw[oc*12 + c*3 + k], xr[c][dmax + k]);
        }
        float cur = s + cc;

        float rst  = (mem - th > 0.f) ? 1.f : 0.f;
        float memn = fmaf(0.5f, mem, cur) - rst*th;
        g_mem0[sidx] = memn;
        float spk = (memn - th > 0.f) ? 1.f : 0.f;
        if (spk > 0.f) mask |= (1u << oc);
        size_t oi = ((size_t)ts*NB + b)*32736 + (size_t)oc*L1 + l1;
        out[O_SPK0 + oi] = spk;
        out[O_MEM0 + oi] = memn;
    }
    g_mask[ts & 1][b*L1 + l1] = mask;
}

// ================= fc body (fc1 + LIF2 + fc2 + LIF3), 256-lane half =========
__device__ __forceinline__ void fc_block(
        char* sm, int ltid, int b, int ts,
        const float* __restrict__ fc1w, const float* __restrict__ fc1b,
        const float* __restrict__ fc2w, const float* __restrict__ fc2b,
        const float* __restrict__ thr, float* __restrict__ out)
{
    float* sfeat = (float*)sm;          // 128
    float* sfc1o = sfeat + 128;         // 256
    float* sspk2 = sfc1o + 256;         // 256

    if (ltid < 128) sfeat[ltid] = g_feat[(size_t)(ts&1)*NB*128 + b*128 + ltid];
    __syncthreads();

    {
        int w = ltid >> 5, lane = ltid & 31;
        for (int oo = 0; oo < 32; oo++) {
            int o = w*32 + oo;
            float s = 0.f, c = 0.f;
            #pragma unroll
            for (int j = 0; j < 4; j++) {
                int f = lane + 32*j;
                kfma(s, c, fc1w[o*128 + f], sfeat[f]);
            }
            #pragma unroll
            for (int sh = 16; sh; sh >>= 1) {
                float s2 = __shfl_down_sync(0xffffffffu, s, sh);
                float c2 = __shfl_down_sync(0xffffffffu, c, sh);
                float ttv, ee;
                twoSum(s, s2, ttv, ee);
                c = (c + c2) + ee;
                s = ttv;
            }
            if (lane == 0) sfc1o[o] = s + c;
        }
    }
    __syncthreads();

    {
        float th = thr[2];
        int o = ltid;
        float cur = sfc1o[o] + fc1b[o];
        float mem  = g_mem2[b*256 + o];
        float rst  = (mem - th > 0.f) ? 1.f : 0.f;
        float memn = fmaf(0.5f, mem, cur) - rst*th;
        g_mem2[b*256 + o] = memn;
        float spk = (memn - th > 0.f) ? 1.f : 0.f;
        sspk2[o] = spk;
        size_t oi = ((size_t)ts*NB + b)*256 + o;
        out[O_SPK2 + oi] = spk;
        out[O_MEM2 + oi] = memn;
    }
    __syncthreads();

    if (ltid < 32) {
        float a0 = 0.f, e0 = 0.f, a1 = 0.f, e1 = 0.f;
        #pragma unroll
        for (int j = 0; j < 8; j++) {
            int o = ltid + 32*j;
            float s = sspk2[o];
            kadd(a0, e0, fc2w[o] * s);
            kadd(a1, e1, fc2w[256 + o] * s);
        }
        #pragma unroll
        for (int sh = 16; sh; sh >>= 1) {
            float s2 = __shfl_down_sync(0xffffffffu, a0, sh);
            float c2 = __shfl_down_sync(0xffffffffu, e0, sh);
            float ttv, ee;
            twoSum(a0, s2, ttv, ee);
            e0 = (e0 + c2) + ee; a0 = ttv;
            s2 = __shfl_down_sync(0xffffffffu, a1, sh);
            c2 = __shfl_down_sync(0xffffffffu, e1, sh);
            twoSum(a1, s2, ttv, ee);
            e1 = (e1 + c2) + ee; a1 = ttv;
        }
        if (ltid == 0) {
            float th = thr[3];
            float cc[2] = {(a0 + e0) + fc2b[0], (a1 + e1) + fc2b[1]};
            #pragma unroll
            for (int r = 0; r < 2; r++) {
                float mem  = g_mem3[b*2 + r];
                float rst  = (mem - th > 0.f) ? 1.f : 0.f;
                float memn = fmaf(0.5f, mem, cc[r]) - rst*th;
                g_mem3[b*2 + r] = memn;
                float spk = (memn - th > 0.f) ? 1.f : 0.f;
                size_t oi = ((size_t)ts*NB + b)*2 + r;
                out[O_SPK3 + oi] = spk;
                out[O_MEM3 + oi] = memn;
            }
        }
    }
}

// ================= stage2 for one batch (LUT resident; 256-lane half) =======
__device__ __forceinline__ void stage2_batch(
        const float4* sT, unsigned* smask, float4* sc, float* saux,
        int ltid, int g, int b, int t,
        const float* __restrict__ b2, const float* __restrict__ thr,
        float* __restrict__ out)
{
    const unsigned* gm = g_mask[t & 1] + b*L1;

    for (int i = ltid; i < 1032; i += 256)
        smask[i] = (i >= 1 && i <= L1) ? gm[i-1] : 0u;
    if (ltid < 8) saux[ltid] = 0.f;
    if (ltid >= 8 && ltid < 12) saux[ltid] = b2[g*4 + (ltid-8)];
    if (ltid == 12) saux[12] = thr[1];

    // prefetch membrane states for pass B (latency hidden by pass A)
    float pm[2][4];
    #pragma unroll
    for (int it = 0; it < 2; it++) {
        int l = ltid + it*256;
        if (l < L2) {
            #pragma unroll
            for (int o = 0; o < 4; o++)
                pm[it][o] = g_mem1[(b*C2 + g*4 + o)*L2 + l];
        }
    }
    __syncthreads();

    // pass A: conv outputs into sc (zero-byte lookups skipped; exact +0)
    {
        int q0 = ltid*4;
        unsigned mm[6];
        #pragma unroll
        for (int j = 0; j < 6; j++) mm[j] = smask[q0 + j];
        #pragma unroll
        for (int i = 0; i < 4; i++) {
            int q = q0 + i;
            if (q < L1) {
                float4 acc = make_float4(0.f, 0.f, 0.f, 0.f);
                #pragma unroll
                for (int k = 0; k < 3; k++) {
                    unsigned m = mm[i + k];
                    unsigned v0 = m & 255u, v1 = (m >> 8) & 255u;
                    unsigned v2 = (m >> 16) & 255u, v3 = m >> 24;
                    const float4* tk = sT + k*4*256;
                    float4 l0 = make_float4(0.f,0.f,0.f,0.f);
                    float4 l1 = l0, l2v = l0, l3 = l0;
                    if (v0) l0  = tk[v0];
                    if (v1) l1  = tk[256 + v1];
                    if (v2) l2v = tk[512 + v2];
                    if (v3) l3  = tk[768 + v3];
                    acc.x += (l0.x + l1.x) + (l2v.x + l3.x);
                    acc.y += (l0.y + l1.y) + (l2v.y + l3.y);
                    acc.z += (l0.z + l1.z) + (l2v.z + l3.z);
                    acc.w += (l0.w + l1.w) + (l2v.w + l3.w);
                }
                sc[q] = acc;
            }
        }
    }
    __syncthreads();

    // pass B: maxpool + LIF1 + writes + spike counts (mem pre-loaded)
    const float th = saux[12];
    const float bs0 = saux[8], bs1 = saux[9], bs2 = saux[10], bs3 = saux[11];
    float cnt0[4] = {0.f,0.f,0.f,0.f}, cnt1[4] = {0.f,0.f,0.f,0.f};

    #pragma unroll
    for (int it = 0; it < 2; it++) {
        int l = ltid + it*256;
        if (l < L2) {
            float4 c0 = sc[2*l], c1 = sc[2*l + 1], c2 = sc[2*l + 2];
            float cur[4];
            cur[0] = fmaxf(c0.x + bs0, fmaxf(c1.x + bs0, c2.x + bs0));
            cur[1] = fmaxf(c0.y + bs1, fmaxf(c1.y + bs1, c2.y + bs1));
            cur[2] = fmaxf(c0.z + bs2, fmaxf(c1.z + bs2, c2.z + bs2));
            cur[3] = fmaxf(c0.w + bs3, fmaxf(c1.w + bs3, c2.w + bs3));
            #pragma unroll
            for (int o = 0; o < 4; o++) {
                int oc = g*4 + o;
                float mem  = pm[it][o];
                float rst  = (mem - th > 0.f) ? 1.f : 0.f;
                float memn = fmaf(0.5f, mem, cur[o]) - rst*th;
                g_mem1[(b*C2 + oc)*L2 + l] = memn;
                float spk = (memn - th > 0.f) ? 1.f : 0.f;
                size_t oi = ((size_t)t*NB + b)*32704 + (size_t)oc*L2 + l;
                out[O_SPK1 + oi] = spk;
                out[O_MEM1 + oi] = memn;
                if (l < 256)  cnt0[o] += spk;
                if (l >= 255) cnt1[o] += spk;
            }
        }
    }

    {
        int lane = ltid & 31;
        #pragma unroll
        for (int o = 0; o < 4; o++) {
            float a = cnt0[o], c = cnt1[o];
            #pragma unroll
            for (int sh = 16; sh; sh >>= 1) {
                a += __shfl_down_sync(0xffffffffu, a, sh);
                c += __shfl_down_sync(0xffffffffu, c, sh);
            }
            if (lane == 0) {
                atomicAdd(&saux[o*2 + 0], a);
                atomicAdd(&saux[o*2 + 1], c);
            }
        }
    }
    __syncthreads();
    if (ltid < 8)
        g_feat[(size_t)(t&1)*NB*128 + b*128 + g*8 + ltid] = saux[ltid] * 0.00390625f;
}

// ================= prologue: stage1 for t = 0 (256 thr) =================
__global__ void __launch_bounds__(256) k_pro(
        const float* __restrict__ x, const float* __restrict__ w1,
        const float* __restrict__ b1, const float* __restrict__ thr,
        float* __restrict__ out)
{
    __shared__ float sw[C1*12];
    __shared__ float sb[C1];
    __shared__ float sthr[1];
    for (int i = threadIdx.x; i < C1*12; i += 256) sw[i] = w1[i];
    if (threadIdx.x < C1) sb[threadIdx.x] = b1[threadIdx.x];
    if (threadIdx.x == 0) sthr[0] = thr[0];
    __syncthreads();
    stage1_task(sw, sb, sthr[0], blockIdx.y, blockIdx.x, 0, threadIdx.x, x, out);
}

// ================= fused (512 thr): stage2(t) + stage1(t+1) + fc(t-1) =======
// blocks [0,256): stage2 (16 g x 16 bquads; each half = 2 serial batches)
// blocks [256,384): stage1(t+1), 2 tile-tasks per block (one per half)
// blocks [384,416): fc(t-1), 2 batches per block (one per half)
__global__ void __launch_bounds__(512, 2) k_fused(
        const float* __restrict__ x,
        const float* __restrict__ w1, const float* __restrict__ b1,
        const float* __restrict__ b2,
        const float* __restrict__ fc1w, const float* __restrict__ fc1b,
        const float* __restrict__ fc2w, const float* __restrict__ fc2b,
        const float* __restrict__ thr, float* __restrict__ out, int t)
{
    extern __shared__ char sm[];
    int bid  = blockIdx.x;
    int tid  = threadIdx.x;
    int half = tid >> 8;
    int ltid = tid & 255;

    if (bid < 256) {
        int g  = bid & 15;
        int bq = bid >> 4;
        float4*   sT    = (float4*)sm;
        char*     hb    = sm + SM_BASE + half*SM_HALF;
        unsigned* smask = (unsigned*)hb;
        float4*   sc    = (float4*)(hb + 4128);
        float*    saux  = (float*)(hb + 4128 + 16368);

        const float4* lutg = (const float4*)g_lut + (size_t)g*12*256;
        for (int i = tid; i < 12*256; i += 512) sT[i] = lutg[i];

        int b0 = bq*4 + half*2;
        stage2_batch(sT, smask, sc, saux, ltid, g, b0 + 0, t, b2, thr, out);
        __syncthreads();
        stage2_batch(sT, smask, sc, saux, ltid, g, b0 + 1, t, b2, thr, out);
    } else if (bid < 384) {
        if (t + 1 < T_STEPS) {
            float* sw = (float*)sm;        // 384
            float* sb = sw + C1*12;        // 32
            float* sthr = sb + C1;
            for (int i = tid; i < C1*12; i += 512) sw[i] = w1[i];
            if (tid < C1) sb[tid] = b1[tid];
            if (tid == 448) sthr[0] = thr[0];
            __syncthreads();
            int r = (bid - 256)*2 + half;   // 0..255
            stage1_task(sw, sb, sthr[0], r >> 2, r & 3, t + 1, ltid, x, out);
        }
    } else {
        if (t >= 1) {
            char* hb = sm + half*2560;
            fc_block(hb, ltid, 2*(bid - 384) + half, t - 1,
                     fc1w, fc1b, fc2w, fc2b, thr, out);
        }
    }
}

// ================= tail: fc for t = 31 (256 thr, one batch/block) ===========
__global__ void __launch_bounds__(256) k_tail(
        const float* __restrict__ fc1w, const float* __restrict__ fc1b,
        const float* __restrict__ fc2w, const float* __restrict__ fc2b,
        const float* __restrict__ thr, float* __restrict__ out)
{
    __shared__ char sm[(128 + 256 + 256) * 4];
    fc_block(sm, threadIdx.x, blockIdx.x, T_STEPS - 1,
             fc1w, fc1b, fc2w, fc2b, thr, out);
}

extern "C" void kernel_launch(void* const* d_in, const int* in_sizes, int n_in,
                              void* d_out, int out_size)
{
    const float* x   = (const float*)d_in[0];
    const float* c1w = (const float*)d_in[1];
    const float* c1b = (const float*)d_in[2];
    const float* c2w = (const float*)d_in[3];
    const float* c2b = (const float*)d_in[4];
    const float* f1w = (const float*)d_in[5];
    const float* f1b = (const float*)d_in[6];
    const float* f2w = (const float*)d_in[7];
    const float* f2b = (const float*)d_in[8];
    const float* thr = (const float*)d_in[9];
    float* out = (float*)d_out;

    cudaFuncSetAttribute(k_fused, cudaFuncAttributeMaxDynamicSharedMemorySize, SMEM2);

    k_init<<<256, 256>>>();
    k_lut<<<768, 256>>>(c2w);
    k_pro<<<dim3(4, NB), 256>>>(x, c1w, c1b, thr, out);
    for (int t = 0; t < T_STEPS; t++) {
        k_fused<<<416, 512, SMEM2>>>(x, c1w, c1b, c2b, f1w, f1b, f2w, f2b,
                                     thr, out, t);
    }
    k_tail<<<NB, 256>>>(f1w, f1b, f2w, f2b, thr, out);
}